// round 12
// baseline (speedup 1.0000x reference)
#include <cuda_runtime.h>
#include <cuda_bf16.h>
#include <math.h>
#include <stdint.h>

// Problem constants
#define B_  16
#define S_  512
#define D_  1024
#define H_  16
#define HD_ 64
#define TOK (B_ * S_)            // 8192 tokens

// Scratch (device globals; no dynamic allocation allowed)
__device__ float g_rope[S_][64];              // [s][0:32)=cos, [32:64)=sin

// bf16 hi|lo operands: A operand [TOK, 2048] (cols 0-1023 hi, 1024-2047 lo)
__device__ __nv_bfloat16 g_xc[(size_t)TOK * 2048];
// weights hi|lo: 4 x [1024, 2048]
__device__ __nv_bfloat16 g_wc[4][(size_t)D_ * 2048];
// prepped attention operands: [bh][plane(hi/lo)][S][64] bf16
__device__ __nv_bfloat16 g_qc[(size_t)B_ * H_ * 2 * S_ * 64];
__device__ __nv_bfloat16 g_kc[(size_t)B_ * H_ * 2 * S_ * 64];
__device__ __nv_bfloat16 g_vc[(size_t)B_ * H_ * 2 * S_ * 64];

#define LOG2E 1.4426950408889634f

// ---------------------------------------------------------------------------
// Helpers (family-portable PTX only: ldmatrix / mma.sync / cp.async)
// ---------------------------------------------------------------------------
__device__ __forceinline__ uint32_t smem_u32(const void* p) {
    uint32_t a;
    asm("{ .reg .u64 t; cvta.to.shared.u64 t, %1; cvt.u32.u64 %0, t; }"
        : "=r"(a) : "l"(p));
    return a;
}

#define SW128(off) ((off) ^ (((off) >> 3) & 0x70))

__device__ __forceinline__ void cp16(uint32_t s, const void* g) {
    asm volatile("cp.async.cg.shared.global [%0], [%1], 16;" :: "r"(s), "l"(g));
}
#define CP_COMMIT() asm volatile("cp.async.commit_group;" ::: "memory")
#define CP_WAIT(n)  asm volatile("cp.async.wait_group %0;" :: "n"(n) : "memory")

#define LDSM_X4(r, addr) \
    asm volatile("ldmatrix.sync.aligned.m8n8.x4.shared.b16 {%0,%1,%2,%3}, [%4];" \
        : "=r"((r)[0]), "=r"((r)[1]), "=r"((r)[2]), "=r"((r)[3]) : "r"(addr))

#define LDSM_X4_T(r, addr) \
    asm volatile("ldmatrix.sync.aligned.m8n8.x4.trans.shared.b16 {%0,%1,%2,%3}, [%4];" \
        : "=r"((r)[0]), "=r"((r)[1]), "=r"((r)[2]), "=r"((r)[3]) : "r"(addr))

#define MMA16816(d, a, b0, b1) \
    asm volatile("mma.sync.aligned.m16n8k16.row.col.f32.bf16.bf16.f32 " \
        "{%0,%1,%2,%3}, {%4,%5,%6,%7}, {%8,%9}, {%0,%1,%2,%3};" \
        : "+f"((d)[0]), "+f"((d)[1]), "+f"((d)[2]), "+f"((d)[3]) \
        : "r"((a)[0]), "r"((a)[1]), "r"((a)[2]), "r"((a)[3]), "r"(b0), "r"(b1))

// Split a pair of floats into packed bf16 hi + bf16 lo (error compensation)
__device__ __forceinline__ void split2(float a, float b, uint32_t& hi, uint32_t& lo) {
    __nv_bfloat16 ah = __float2bfloat16_rn(a);
    __nv_bfloat16 bh = __float2bfloat16_rn(b);
    float ar = a - __bfloat162float(ah);
    float br = b - __bfloat162float(bh);
    __nv_bfloat162 hp; hp.x = ah; hp.y = bh;
    __nv_bfloat162 lp; lp.x = __float2bfloat16_rn(ar); lp.y = __float2bfloat16_rn(br);
    hi = *(uint32_t*)&hp;
    lo = *(uint32_t*)&lp;
}

// ---------------------------------------------------------------------------
// Merged input prep: convert x (blocks 0..4095), convert weights
// (blocks 4096..6143), rope table (blocks 6144..6207). One launch.
// ---------------------------------------------------------------------------
__device__ __forceinline__ void conv_row_body(const float* __restrict__ s,
                                              __nv_bfloat16* __restrict__ dst,
                                              int row, int c8)
{
    float4 v0 = *(const float4*)(s);
    float4 v1 = *(const float4*)(s + 4);
    float vs[8] = {v0.x, v0.y, v0.z, v0.w, v1.x, v1.y, v1.z, v1.w};

    uint32_t hw[4], lw[4];
#pragma unroll
    for (int j = 0; j < 4; j++) split2(vs[2 * j], vs[2 * j + 1], hw[j], lw[j]);

    uint4* dh = (uint4*)(dst + (size_t)row * 2048 + c8);
    uint4* dl = (uint4*)(dst + (size_t)row * 2048 + 1024 + c8);
    *dh = make_uint4(hw[0], hw[1], hw[2], hw[3]);
    *dl = make_uint4(lw[0], lw[1], lw[2], lw[3]);
}

__global__ void prep_inputs(const float* __restrict__ x,
                            const float* __restrict__ w0, const float* __restrict__ w1,
                            const float* __restrict__ w2, const float* __restrict__ w3)
{
    const int blk = blockIdx.x;
    const int tid = threadIdx.x;

    if (blk < 4096) {
        // convert x -> g_xc
        int i = blk * 256 + tid;
        int row = i >> 7;
        int c8 = (i & 127) * 8;
        conv_row_body(x + (size_t)row * 1024 + c8, g_xc, row, c8);
    } else if (blk < 6144) {
        // convert weights -> g_wc
        int wb = blk - 4096;
        int which = wb >> 9;              // 0..3
        int i = (wb & 511) * 256 + tid;
        int row = i >> 7;
        int c8 = (i & 127) * 8;
        const float* src = (which == 0) ? w0 : (which == 1) ? w1
                         : (which == 2) ? w2 : w3;
        conv_row_body(src + (size_t)row * 1024 + c8, g_wc[which], row, c8);
    } else {
        // rope table
        int t = (blk - 6144) * 256 + tid;   // 512*32
        int d = t & 31;
        int s = t >> 5;
        float inv = expf(-(float)d * (9.210340371976184f / 32.0f));
        float ang = (float)s * inv;
        float sn, cs;
        sincosf(ang, &sn, &cs);
        g_rope[s][d] = cs;
        g_rope[s][d + 32] = sn;
    }
}

// ---------------------------------------------------------------------------
// bf16 hi/lo plane write for attention operands (x[0..15]=cols c0..,
// x[16..31]=cols c0+32..), dst layout [plane][S][64].
// ---------------------------------------------------------------------------
__device__ __forceinline__ void prep_write(const float* __restrict__ x,
                                           __nv_bfloat16* __restrict__ basehi,
                                           int s, int c0)
{
    uint32_t hi[16], lo[16];
#pragma unroll
    for (int p = 0; p < 8; p++)  split2(x[2 * p], x[2 * p + 1], hi[p], lo[p]);
#pragma unroll
    for (int p = 0; p < 8; p++)  split2(x[16 + 2 * p], x[17 + 2 * p], hi[8 + p], lo[8 + p]);

    __nv_bfloat16* ph = basehi + (size_t)s * 64;
    __nv_bfloat16* pl = basehi + (size_t)S_ * 64 + (size_t)s * 64;
    *(uint4*)(ph + c0)      = make_uint4(hi[0], hi[1], hi[2], hi[3]);
    *(uint4*)(ph + c0 + 8)  = make_uint4(hi[4], hi[5], hi[6], hi[7]);
    *(uint4*)(ph + c0 + 32) = make_uint4(hi[8], hi[9], hi[10], hi[11]);
    *(uint4*)(ph + c0 + 40) = make_uint4(hi[12], hi[13], hi[14], hi[15]);
    *(uint4*)(pl + c0)      = make_uint4(lo[0], lo[1], lo[2], lo[3]);
    *(uint4*)(pl + c0 + 8)  = make_uint4(lo[4], lo[5], lo[6], lo[7]);
    *(uint4*)(pl + c0 + 32) = make_uint4(lo[8], lo[9], lo[10], lo[11]);
    *(uint4*)(pl + c0 + 40) = make_uint4(lo[12], lo[13], lo[14], lo[15]);
}

// ---------------------------------------------------------------------------
// HMMA GEMM: C[m,n] = sum_k A[m,k]*W[n,k], bf16x3 split (K' = 3072).
// CTA 128x128 (8 warps, warp tile 64x32), 3-stage cp.async ring, SW128,
// single __syncthreads per chunk, 2 CTAs/SM (<=128 regs).
// QKV variant: fused RoPE + bf16 hi/lo split epilogue -> g_qc/g_kc/g_vc.
// OUT variant: Wo, plain fp32 write.
// ---------------------------------------------------------------------------
#define NCHUNK 48                 // 3 segments x 16 chunks of K=64
#define TILE_BYTES 16384          // 128 rows x 128 bytes
#define BUF_BYTES  (2 * TILE_BYTES)
#define NSTAGE 3
#define GEMM_SMEM  (NSTAGE * BUF_BYTES)   // 98304

template<bool QKV>
__device__ __forceinline__ void gemm_body(float* __restrict__ out, int zmode)
{
    extern __shared__ char smc[];
    const uint32_t smem_base = smem_u32(smc);
    const int tid  = threadIdx.x;
    const int wid  = tid >> 5;
    const int lane = tid & 31;
    const int wm   = wid >> 2;      // 0..1
    const int wn   = wid & 3;       // 0..3

    const int n0 = blockIdx.x * 128;
    const int m0 = blockIdx.y * 128;

    const __nv_bfloat16* __restrict__ Wsrc = g_wc[QKV ? zmode : 3];

    const int r0  = tid >> 3;
    const int c16 = tid & 7;
    const __nv_bfloat16* aGm0 = g_xc + (size_t)(m0 + r0) * 2048 + c16 * 8;
    const __nv_bfloat16* bGm0 = Wsrc + (size_t)(n0 + r0) * 2048 + c16 * 8;
    const uint32_t aSm0 = SW128((uint32_t)(r0 * 128 + c16 * 16));
    const uint32_t bSm0 = TILE_BYTES + SW128((uint32_t)(r0 * 128 + c16 * 16));

    uint32_t aRow[4];
#pragma unroll
    for (int i = 0; i < 4; i++)
        aRow[i] = (uint32_t)((wm * 64 + i * 16 + (lane & 15)) * 128 + (lane >> 4) * 16);
    uint32_t bRow[2];
#pragma unroll
    for (int g = 0; g < 2; g++)
        bRow[g] = (uint32_t)(TILE_BYTES +
                  (wn * 32 + g * 16 + ((lane >> 4) & 1) * 8 + (lane & 7)) * 128 +
                  ((lane >> 3) & 1) * 16);

    float acc[4][4][4];
#pragma unroll
    for (int i = 0; i < 4; i++)
#pragma unroll
        for (int j = 0; j < 4; j++)
#pragma unroll
            for (int r = 0; r < 4; r++) acc[i][j][r] = 0.f;

    auto issue = [&](int c) {
        const int seg = c >> 4;
        const int kc  = (c & 15) * 64;
        const int ka  = kc + ((seg == 2) ? 1024 : 0);
        const int kb  = kc + ((seg == 1) ? 1024 : 0);
        const uint32_t base = smem_base + (uint32_t)(c % NSTAGE) * BUF_BYTES;
#pragma unroll
        for (int i = 0; i < 4; i++)
            cp16(base + aSm0 + i * 4096u, aGm0 + ka + (size_t)i * 32 * 2048);
#pragma unroll
        for (int i = 0; i < 4; i++)
            cp16(base + bSm0 + i * 4096u, bGm0 + kb + (size_t)i * 32 * 2048);
        CP_COMMIT();
    };

    issue(0);
    issue(1);

    for (int c = 0; c < NCHUNK; c++) {
        if (c + 2 < NCHUNK) {
            CP_WAIT(1);
            __syncthreads();      // stage c visible; all warps done with stage c-1
            issue(c + 2);         // overwrites stage (c-1)%3 — safe after sync
        } else {
            CP_WAIT(0);
            __syncthreads();
        }

        const uint32_t base = smem_base + (uint32_t)(c % NSTAGE) * BUF_BYTES;
#pragma unroll
        for (int ks = 0; ks < 4; ks++) {
            const uint32_t kb32 = (uint32_t)(ks * 32);
            uint32_t af[4][4], bf[2][4];
#pragma unroll
            for (int i = 0; i < 4; i++)
                LDSM_X4(af[i], base + SW128(aRow[i] + kb32));
#pragma unroll
            for (int g = 0; g < 2; g++)
                LDSM_X4(bf[g], base + SW128(bRow[g] + kb32));
#pragma unroll
            for (int i = 0; i < 4; i++) {
#pragma unroll
                for (int j = 0; j < 4; j++) {
                    const uint32_t* bb = bf[j >> 1];
                    MMA16816(acc[i][j], af[i], bb[(j & 1) * 2], bb[(j & 1) * 2 + 1]);
                }
            }
        }
    }

    const int r4 = lane >> 2;
    const int c2 = (lane & 3) * 2;

    if (!QKV) {
        // Plain fp32 epilogue
#pragma unroll
        for (int i = 0; i < 4; i++) {
            const int mbase = m0 + wm * 64 + i * 16 + r4;
#pragma unroll
            for (int j = 0; j < 4; j++) {
                const int n = n0 + wn * 32 + j * 8 + c2;
#pragma unroll
                for (int rr = 0; rr < 2; rr++) {
                    const int m = mbase + rr * 8;
                    float2 val;
                    val.x = acc[i][j][rr * 2 + 0];
                    val.y = acc[i][j][rr * 2 + 1];
                    *(float2*)(out + (size_t)m * D_ + n) = val;
                }
            }
        }
        return;
    }

    // ---- Fused QKV epilogue: stage fp32 tile via ring smem, rope + split ----
    __syncthreads();              // all warps done with last LDSM reads
    float* sf = (float*)smc;      // reuse ring: 128 x 132 fp32 (67.5 KB)
#pragma unroll
    for (int i = 0; i < 4; i++) {
#pragma unroll
        for (int j = 0; j < 4; j++) {
            const int nl = wn * 32 + j * 8 + c2;
#pragma unroll
            for (int rr = 0; rr < 2; rr++) {
                const int ml = wm * 64 + i * 16 + rr * 8 + r4;
                sf[ml * 132 + nl]     = acc[i][j][rr * 2 + 0];
                sf[ml * 132 + nl + 1] = acc[i][j][rr * 2 + 1];
            }
        }
    }
    __syncthreads();

    __nv_bfloat16* dstbase = (zmode == 0) ? g_qc : (zmode == 1) ? g_kc : g_vc;

#pragma unroll
    for (int it = 0; it < 2; it++) {
        const int u    = tid + 256 * it;       // 512 units: 128 rows x 2 heads x 2 halves
        const int r    = u >> 2;
        const int hh   = (u >> 1) & 1;
        const int half = u & 1;
        const int c0   = half * 16;

        const int m = m0 + r;
        const int s = m & 511;
        const int bcur = m >> 9;
        const int hglob = (n0 >> 6) + hh;
        const size_t plane = (size_t)(bcur * H_ + hglob) * 2 * S_ * 64;

        const float* srow = sf + r * 132 + hh * 64;
        float x[32];
#pragma unroll
        for (int j2 = 0; j2 < 4; j2++) {
            *(float4*)&x[j2 * 4]      = *(const float4*)(srow + c0 + j2 * 4);
            *(float4*)&x[16 + j2 * 4] = *(const float4*)(srow + c0 + 32 + j2 * 4);
        }

        if (zmode != 2) {
            const float* tab = g_rope[s];
            const float sc = (zmode == 0) ? 0.125f : 1.0f;
#pragma unroll
            for (int j2 = 0; j2 < 16; j2++) {
                const float csv = tab[c0 + j2] * sc;
                const float snv = tab[c0 + j2 + 32] * sc;
                const float a = x[j2], b2v = x[16 + j2];
                x[j2]      = a * csv - b2v * snv;
                x[16 + j2] = b2v * csv + a * snv;
            }
        }
        prep_write(x, dstbase + plane, s, c0);
    }
}

__global__ void __launch_bounds__(256, 2) gemm_qkv()
{
    gemm_body<true>(nullptr, blockIdx.z);
}

__global__ void __launch_bounds__(256, 2) gemm_out(float* __restrict__ out)
{
    gemm_body<false>(out, 3);
}

// ---------------------------------------------------------------------------
// HMMA causal flash attention, 128-query CTA tile (8 warps, 256 threads).
// Warp w owns q rows [q0 + w*16, +16). Key blocks of 64, 3-stage KV ring.
// smem: Q (QH 16KB | QL 16KB) then 3 KV stages of 32KB (KH|KL|VH|VL).
// Halves KV gmem traffic vs 64-query tile; 1 CTA/SM (8 warps, same as before).
// ---------------------------------------------------------------------------
#define ATT_ST   32768
#define ATT_STB  32768
#define ATT_SMEM (ATT_ST + 3 * ATT_STB)   // 131072

// cp.async one ROWSx64 bf16 plane into SW128-swizzled smem (256 threads)
template<int ROWS>
__device__ __forceinline__ void cpa_plane(uint32_t dst, const __nv_bfloat16* __restrict__ src,
                                          int tid)
{
#pragma unroll
    for (int i = 0; i < ROWS * 8 / 256; i++) {
        int u = tid + 256 * i;
        int r = u >> 3, ch = u & 7;
        cp16(dst + SW128((uint32_t)(r * 128 + ch * 16)), src + (size_t)r * 64 + ch * 8);
    }
}

__global__ void __launch_bounds__(256) attn_mma()
{
    extern __shared__ char sm[];
    const uint32_t sb = smem_u32(sm);

    const int tid  = threadIdx.x;
    const int lane = tid & 31;
    const int w    = tid >> 5;          // 0..7
    const int qb = (S_ / 128 - 1) - blockIdx.x;   // heavy blocks first
    const int h  = blockIdx.y;
    const int b  = blockIdx.z;
    const int q0 = qb * 128;
    const int bh = b * H_ + h;

    const size_t plane = (size_t)bh * 2 * S_ * 64;
    const size_t LO = (size_t)S_ * 64;
    const __nv_bfloat16* Qc = g_qc + plane;
    const __nv_bfloat16* Kc = g_kc + plane;
    const __nv_bfloat16* Vc = g_vc + plane;

    const int i7  = lane & 7;
    const int grp = lane >> 3;
    const int nkb = 2 * qb + 2;         // 64-wide key tiles covering [0, q0+128)

    auto issue_kv = [&](int kb) {
        const uint32_t st = sb + ATT_ST + (uint32_t)(kb % 3) * ATT_STB;
        const int k0 = kb * 64;
        cpa_plane<64>(st,         Kc + (size_t)k0 * 64,      tid);
        cpa_plane<64>(st + 8192,  Kc + LO + (size_t)k0 * 64, tid);
        cpa_plane<64>(st + 16384, Vc + (size_t)k0 * 64,      tid);
        cpa_plane<64>(st + 24576, Vc + LO + (size_t)k0 * 64, tid);
        CP_COMMIT();
    };

    // group 0: Q (128x64 hi+lo) + KV stage 0;  group 1: KV stage 1
    cpa_plane<128>(sb,         Qc + (size_t)q0 * 64,      tid);
    cpa_plane<128>(sb + 16384, Qc + LO + (size_t)q0 * 64, tid);
    {
        const uint32_t st = sb + ATT_ST;
        cpa_plane<64>(st,         Kc,      tid);
        cpa_plane<64>(st + 8192,  Kc + LO, tid);
        cpa_plane<64>(st + 16384, Vc,      tid);
        cpa_plane<64>(st + 24576, Vc + LO, tid);
        CP_COMMIT();
    }
    if (nkb > 1) issue_kv(1);

    uint32_t qh[4][4], ql[4][4];
    float mr0 = -1e30f, mr1 = -1e30f;
    float l0 = 0.f, l1 = 0.f;
    float O[8][4];
#pragma unroll
    for (int i = 0; i < 8; i++)
#pragma unroll
        for (int j = 0; j < 4; j++) O[i][j] = 0.f;

    for (int kb = 0; kb < nkb; kb++) {
        if (kb + 1 < nkb) { CP_WAIT(1); } else { CP_WAIT(0); }
        __syncthreads();
        if (kb + 2 < nkb) issue_kv(kb + 2);

        if (kb == 0) {
            // Q fragments (once) — rows within the 128-row Q planes
            const int m0 = w * 16;
#pragma unroll
            for (int kc = 0; kc < 4; kc++) {
                const int row = m0 + (grp & 1) * 8 + i7;
                const uint32_t kbyte = (uint32_t)(kc * 32 + (grp >> 1) * 16);
                LDSM_X4(qh[kc], sb + SW128((uint32_t)(row * 128) + kbyte));
                LDSM_X4(ql[kc], sb + 16384 + SW128((uint32_t)(row * 128) + kbyte));
            }
        }

        const uint32_t st = sb + ATT_ST + (uint32_t)(kb % 3) * ATT_STB;
        const uint32_t KH = st, KL = st + 8192, VH = st + 16384, VL = st + 24576;
        const int k0 = kb * 64;

        // ---- Scores S[16q x 64k] per warp, 3 error-comp passes ----
        float S[8][4];
#pragma unroll
        for (int i = 0; i < 8; i++)
#pragma unroll
            for (int j = 0; j < 4; j++) S[i][j] = 0.f;

#pragma unroll
        for (int kc = 0; kc < 4; kc++) {
#pragma unroll
            for (int n2 = 0; n2 < 4; n2++) {
                const int row = n2 * 16 + (grp >> 1) * 8 + i7;
                const uint32_t kbyte = (uint32_t)(kc * 32 + (grp & 1) * 16);
                uint32_t bhf[4], blf[4];
                LDSM_X4(bhf, KH + SW128((uint32_t)(row * 128) + kbyte));
                LDSM_X4(blf, KL + SW128((uint32_t)(row * 128) + kbyte));
                MMA16816(S[n2 * 2],     qh[kc], bhf[0], bhf[1]);
                MMA16816(S[n2 * 2 + 1], qh[kc], bhf[2], bhf[3]);
                MMA16816(S[n2 * 2],     ql[kc], bhf[0], bhf[1]);
                MMA16816(S[n2 * 2 + 1], ql[kc], bhf[2], bhf[3]);
                MMA16816(S[n2 * 2],     qh[kc], blf[0], blf[1]);
                MMA16816(S[n2 * 2 + 1], qh[kc], blf[2], blf[3]);
            }
        }

        // ---- Causal mask (global compare; tiles beyond warp's rows fully mask)
        // Safe: tile kb=0 always has valid k for every q row, so the running
        // max is finite before any fully-masked tile (corr=1, P=0 exactly).
        {
            const int rg0 = q0 + w * 16 + (lane >> 2);   // global q row (frag row 0)
            const int cbase = k0 + (lane & 3) * 2;       // global k col base
#pragma unroll
            for (int jt = 0; jt < 8; jt++) {
                const int c = jt * 8 + cbase;
                if (c     > rg0)     S[jt][0] = -1e30f;
                if (c + 1 > rg0)     S[jt][1] = -1e30f;
                if (c     > rg0 + 8) S[jt][2] = -1e30f;
                if (c + 1 > rg0 + 8) S[jt][3] = -1e30f;
            }
        }

        // ---- Online softmax ----
        float bm0 = -1e30f, bm1 = -1e30f;
#pragma unroll
        for (int jt = 0; jt < 8; jt++) {
            bm0 = fmaxf(bm0, fmaxf(S[jt][0], S[jt][1]));
            bm1 = fmaxf(bm1, fmaxf(S[jt][2], S[jt][3]));
        }
        bm0 = fmaxf(bm0, __shfl_xor_sync(0xFFFFFFFF, bm0, 1));
        bm0 = fmaxf(bm0, __shfl_xor_sync(0xFFFFFFFF, bm0, 2));
        bm1 = fmaxf(bm1, __shfl_xor_sync(0xFFFFFFFF, bm1, 1));
        bm1 = fmaxf(bm1, __shfl_xor_sync(0xFFFFFFFF, bm1, 2));

        const float mn0 = fmaxf(mr0, bm0);
        const float mn1 = fmaxf(mr1, bm1);
        const float corr0 = exp2f((mr0 - mn0) * LOG2E);
        const float corr1 = exp2f((mr1 - mn1) * LOG2E);
        mr0 = mn0; mr1 = mn1;
        l0 *= corr0; l1 *= corr1;

        float P[8][4];
#pragma unroll
        for (int jt = 0; jt < 8; jt++) {
            P[jt][0] = exp2f((S[jt][0] - mn0) * LOG2E);
            P[jt][1] = exp2f((S[jt][1] - mn0) * LOG2E);
            P[jt][2] = exp2f((S[jt][2] - mn1) * LOG2E);
            P[jt][3] = exp2f((S[jt][3] - mn1) * LOG2E);
            l0 += P[jt][0] + P[jt][1];
            l1 += P[jt][2] + P[jt][3];
        }
#pragma unroll
        for (int dt = 0; dt < 8; dt++) {
            O[dt][0] *= corr0; O[dt][1] *= corr0;
            O[dt][2] *= corr1; O[dt][3] *= corr1;
        }

        // ---- P A-fragments (hi/lo) from C-fragment layout ----
        uint32_t ph[4][4], pl[4][4];
#pragma unroll
        for (int kc = 0; kc < 4; kc++) {
            split2(P[2 * kc][0],     P[2 * kc][1],     ph[kc][0], pl[kc][0]);
            split2(P[2 * kc][2],     P[2 * kc][3],     ph[kc][1], pl[kc][1]);
            split2(P[2 * kc + 1][0], P[2 * kc + 1][1], ph[kc][2], pl[kc][2]);
            split2(P[2 * kc + 1][2], P[2 * kc + 1][3], ph[kc][3], pl[kc][3]);
        }

        // ---- PV, 3 error-comp passes (V via ldmatrix.trans) ----
#pragma unroll
        for (int kc = 0; kc < 4; kc++) {
#pragma unroll
            for (int d2 = 0; d2 < 4; d2++) {
                const int row = kc * 16 + (grp & 1) * 8 + i7;
                const uint32_t dbyte = (uint32_t)(d2 * 32 + (grp >> 1) * 16);
                uint32_t bhf[4], blf[4];
                LDSM_X4_T(bhf, VH + SW128((uint32_t)(row * 128) + dbyte));
                LDSM_X4_T(blf, VL + SW128((uint32_t)(row * 128) + dbyte));
                MMA16816(O[d2 * 2],     ph[kc], bhf[0], bhf[1]);
                MMA16816(O[d2 * 2 + 1], ph[kc], bhf[2], bhf[3]);
                MMA16816(O[d2 * 2],     pl[kc], bhf[0], bhf[1]);
                MMA16816(O[d2 * 2 + 1], pl[kc], bhf[2], bhf[3]);
                MMA16816(O[d2 * 2],     ph[kc], blf[0], blf[1]);
                MMA16816(O[d2 * 2 + 1], ph[kc], blf[2], blf[3]);
            }
        }
    }

    // ---- Final l reduction + normalized bf16 hi/lo write to g_xc ----
    l0 += __shfl_xor_sync(0xFFFFFFFF, l0, 1);
    l0 += __shfl_xor_sync(0xFFFFFFFF, l0, 2);
    l1 += __shfl_xor_sync(0xFFFFFFFF, l1, 1);
    l1 += __shfl_xor_sync(0xFFFFFFFF, l1, 2);
    const float inv0 = 1.0f / l0;
    const float inv1 = 1.0f / l1;

    const int rA = q0 + w * 16 + (lane >> 2);
    const int rB = rA + 8;
    const size_t tA = ((size_t)(b * S_ + rA)) * 2048;
    const size_t tB = ((size_t)(b * S_ + rB)) * 2048;
    const int colbase = h * 64 + (lane & 3) * 2;

#pragma unroll
    for (int dt = 0; dt < 8; dt++) {
        const int col = colbase + dt * 8;
        uint32_t hi, lo;
        split2(O[dt][0] * inv0, O[dt][1] * inv0, hi, lo);
        *(uint32_t*)&g_xc[tA + col]        = hi;
        *(uint32_t*)&g_xc[tA + 1024 + col] = lo;
        split2(O[dt][2] * inv1, O[dt][3] * inv1, hi, lo);
        *(uint32_t*)&g_xc[tB + col]        = hi;
        *(uint32_t*)&g_xc[tB + 1024 + col] = lo;
    }
}

// ---------------------------------------------------------------------------
extern "C" void kernel_launch(void* const* d_in, const int* in_sizes, int n_in,
                              void* d_out, int out_size)
{
    const float* x  = (const float*)d_in[0];
    const float* Wq = (const float*)d_in[1];
    const float* Wk = (const float*)d_in[2];
    const float* Wv = (const float*)d_in[3];
    const float* Wo = (const float*)d_in[4];
    float* out = (float*)d_out;

    cudaFuncSetAttribute(gemm_qkv, cudaFuncAttributeMaxDynamicSharedMemorySize, GEMM_SMEM);
    cudaFuncSetAttribute(gemm_out, cudaFuncAttributeMaxDynamicSharedMemorySize, GEMM_SMEM);
    cudaFuncSetAttribute(attn_mma, cudaFuncAttributeMaxDynamicSharedMemorySize, ATT_SMEM);

    // One merged prep launch: x-convert | weight-converts | rope table
    prep_inputs<<<6208, 256>>>(x, Wq, Wk, Wv, Wo);

    // Merged QKV projections with fused RoPE + bf16 split epilogue
    gemm_qkv<<<dim3(D_ / 128, TOK / 128, 3), 256, GEMM_SMEM>>>();

    attn_mma<<<dim3(S_ / 128, H_, B_), 256, ATT_SMEM>>>();

    gemm_out<<<dim3(D_ / 128, TOK / 128), 256, GEMM_SMEM>>>(out);
}

// round 13
// speedup vs baseline: 1.0293x; 1.0293x over previous
#include <cuda_runtime.h>
#include <cuda_bf16.h>
#include <math.h>
#include <stdint.h>

// Problem constants
#define B_  16
#define S_  512
#define D_  1024
#define H_  16
#define HD_ 64
#define TOK (B_ * S_)            // 8192 tokens

// Scratch (device globals; no dynamic allocation allowed)
__device__ float g_rope[S_][64];              // [s][0:32)=cos, [32:64)=sin

// bf16 hi|lo operands: A operand [TOK, 2048] (cols 0-1023 hi, 1024-2047 lo)
__device__ __nv_bfloat16 g_xc[(size_t)TOK * 2048];
// weights hi|lo: 4 x [1024, 2048]
__device__ __nv_bfloat16 g_wc[4][(size_t)D_ * 2048];
// prepped attention operands: [bh][plane(hi/lo)][S][64] bf16
__device__ __nv_bfloat16 g_qc[(size_t)B_ * H_ * 2 * S_ * 64];
__device__ __nv_bfloat16 g_kc[(size_t)B_ * H_ * 2 * S_ * 64];
__device__ __nv_bfloat16 g_vc[(size_t)B_ * H_ * 2 * S_ * 64];

#define LOG2E 1.4426950408889634f

// ---------------------------------------------------------------------------
// Helpers (family-portable PTX only: ldmatrix / mma.sync / cp.async)
// ---------------------------------------------------------------------------
__device__ __forceinline__ uint32_t smem_u32(const void* p) {
    uint32_t a;
    asm("{ .reg .u64 t; cvta.to.shared.u64 t, %1; cvt.u32.u64 %0, t; }"
        : "=r"(a) : "l"(p));
    return a;
}

#define SW128(off) ((off) ^ (((off) >> 3) & 0x70))

__device__ __forceinline__ void cp16(uint32_t s, const void* g) {
    asm volatile("cp.async.cg.shared.global [%0], [%1], 16;" :: "r"(s), "l"(g));
}
#define CP_COMMIT() asm volatile("cp.async.commit_group;" ::: "memory")
#define CP_WAIT(n)  asm volatile("cp.async.wait_group %0;" :: "n"(n) : "memory")

#define LDSM_X4(r, addr) \
    asm volatile("ldmatrix.sync.aligned.m8n8.x4.shared.b16 {%0,%1,%2,%3}, [%4];" \
        : "=r"((r)[0]), "=r"((r)[1]), "=r"((r)[2]), "=r"((r)[3]) : "r"(addr))

#define LDSM_X4_T(r, addr) \
    asm volatile("ldmatrix.sync.aligned.m8n8.x4.trans.shared.b16 {%0,%1,%2,%3}, [%4];" \
        : "=r"((r)[0]), "=r"((r)[1]), "=r"((r)[2]), "=r"((r)[3]) : "r"(addr))

#define MMA16816(d, a, b0, b1) \
    asm volatile("mma.sync.aligned.m16n8k16.row.col.f32.bf16.bf16.f32 " \
        "{%0,%1,%2,%3}, {%4,%5,%6,%7}, {%8,%9}, {%0,%1,%2,%3};" \
        : "+f"((d)[0]), "+f"((d)[1]), "+f"((d)[2]), "+f"((d)[3]) \
        : "r"((a)[0]), "r"((a)[1]), "r"((a)[2]), "r"((a)[3]), "r"(b0), "r"(b1))

// Split a pair of floats into packed bf16 hi + bf16 lo (error compensation)
__device__ __forceinline__ void split2(float a, float b, uint32_t& hi, uint32_t& lo) {
    __nv_bfloat16 ah = __float2bfloat16_rn(a);
    __nv_bfloat16 bh = __float2bfloat16_rn(b);
    float ar = a - __bfloat162float(ah);
    float br = b - __bfloat162float(bh);
    __nv_bfloat162 hp; hp.x = ah; hp.y = bh;
    __nv_bfloat162 lp; lp.x = __float2bfloat16_rn(ar); lp.y = __float2bfloat16_rn(br);
    hi = *(uint32_t*)&hp;
    lo = *(uint32_t*)&lp;
}

// ---------------------------------------------------------------------------
// Merged input prep: convert x (blocks 0..4095), convert weights
// (blocks 4096..6143), rope table (blocks 6144..6207). One launch.
// ---------------------------------------------------------------------------
__device__ __forceinline__ void conv_row_body(const float* __restrict__ s,
                                              __nv_bfloat16* __restrict__ dst,
                                              int row, int c8)
{
    float4 v0 = *(const float4*)(s);
    float4 v1 = *(const float4*)(s + 4);
    float vs[8] = {v0.x, v0.y, v0.z, v0.w, v1.x, v1.y, v1.z, v1.w};

    uint32_t hw[4], lw[4];
#pragma unroll
    for (int j = 0; j < 4; j++) split2(vs[2 * j], vs[2 * j + 1], hw[j], lw[j]);

    uint4* dh = (uint4*)(dst + (size_t)row * 2048 + c8);
    uint4* dl = (uint4*)(dst + (size_t)row * 2048 + 1024 + c8);
    *dh = make_uint4(hw[0], hw[1], hw[2], hw[3]);
    *dl = make_uint4(lw[0], lw[1], lw[2], lw[3]);
}

__global__ void prep_inputs(const float* __restrict__ x,
                            const float* __restrict__ w0, const float* __restrict__ w1,
                            const float* __restrict__ w2, const float* __restrict__ w3)
{
    const int blk = blockIdx.x;
    const int tid = threadIdx.x;

    if (blk < 4096) {
        // convert x -> g_xc
        int i = blk * 256 + tid;
        int row = i >> 7;
        int c8 = (i & 127) * 8;
        conv_row_body(x + (size_t)row * 1024 + c8, g_xc, row, c8);
    } else if (blk < 6144) {
        // convert weights -> g_wc
        int wb = blk - 4096;
        int which = wb >> 9;              // 0..3
        int i = (wb & 511) * 256 + tid;
        int row = i >> 7;
        int c8 = (i & 127) * 8;
        const float* src = (which == 0) ? w0 : (which == 1) ? w1
                         : (which == 2) ? w2 : w3;
        conv_row_body(src + (size_t)row * 1024 + c8, g_wc[which], row, c8);
    } else {
        // rope table
        int t = (blk - 6144) * 256 + tid;   // 512*32
        int d = t & 31;
        int s = t >> 5;
        float inv = expf(-(float)d * (9.210340371976184f / 32.0f));
        float ang = (float)s * inv;
        float sn, cs;
        sincosf(ang, &sn, &cs);
        g_rope[s][d] = cs;
        g_rope[s][d + 32] = sn;
    }
}

// ---------------------------------------------------------------------------
// bf16 hi/lo plane write for attention operands (x[0..15]=cols c0..,
// x[16..31]=cols c0+32..), dst layout [plane][S][64].
// ---------------------------------------------------------------------------
__device__ __forceinline__ void prep_write(const float* __restrict__ x,
                                           __nv_bfloat16* __restrict__ basehi,
                                           int s, int c0)
{
    uint32_t hi[16], lo[16];
#pragma unroll
    for (int p = 0; p < 8; p++)  split2(x[2 * p], x[2 * p + 1], hi[p], lo[p]);
#pragma unroll
    for (int p = 0; p < 8; p++)  split2(x[16 + 2 * p], x[17 + 2 * p], hi[8 + p], lo[8 + p]);

    __nv_bfloat16* ph = basehi + (size_t)s * 64;
    __nv_bfloat16* pl = basehi + (size_t)S_ * 64 + (size_t)s * 64;
    *(uint4*)(ph + c0)      = make_uint4(hi[0], hi[1], hi[2], hi[3]);
    *(uint4*)(ph + c0 + 8)  = make_uint4(hi[4], hi[5], hi[6], hi[7]);
    *(uint4*)(ph + c0 + 32) = make_uint4(hi[8], hi[9], hi[10], hi[11]);
    *(uint4*)(ph + c0 + 40) = make_uint4(hi[12], hi[13], hi[14], hi[15]);
    *(uint4*)(pl + c0)      = make_uint4(lo[0], lo[1], lo[2], lo[3]);
    *(uint4*)(pl + c0 + 8)  = make_uint4(lo[4], lo[5], lo[6], lo[7]);
    *(uint4*)(pl + c0 + 32) = make_uint4(lo[8], lo[9], lo[10], lo[11]);
    *(uint4*)(pl + c0 + 40) = make_uint4(lo[12], lo[13], lo[14], lo[15]);
}

// ---------------------------------------------------------------------------
// HMMA GEMM: C[m,n] = sum_k A[m,k]*W[n,k], bf16x3 split (K' = 3072).
// CTA 128x128 (8 warps, warp tile 64x32), 3-stage cp.async ring, SW128,
// single __syncthreads per chunk, 2 CTAs/SM (<=128 regs).
// QKV variant: fused RoPE + bf16 hi/lo split epilogue -> g_qc/g_kc/g_vc.
// OUT variant: Wo, plain fp32 write.
// ---------------------------------------------------------------------------
#define NCHUNK 48                 // 3 segments x 16 chunks of K=64
#define TILE_BYTES 16384          // 128 rows x 128 bytes
#define BUF_BYTES  (2 * TILE_BYTES)
#define NSTAGE 3
#define GEMM_SMEM  (NSTAGE * BUF_BYTES)   // 98304

template<bool QKV>
__device__ __forceinline__ void gemm_body(float* __restrict__ out, int zmode)
{
    extern __shared__ char smc[];
    const uint32_t smem_base = smem_u32(smc);
    const int tid  = threadIdx.x;
    const int wid  = tid >> 5;
    const int lane = tid & 31;
    const int wm   = wid >> 2;      // 0..1
    const int wn   = wid & 3;       // 0..3

    const int n0 = blockIdx.x * 128;
    const int m0 = blockIdx.y * 128;

    const __nv_bfloat16* __restrict__ Wsrc = g_wc[QKV ? zmode : 3];

    const int r0  = tid >> 3;
    const int c16 = tid & 7;
    const __nv_bfloat16* aGm0 = g_xc + (size_t)(m0 + r0) * 2048 + c16 * 8;
    const __nv_bfloat16* bGm0 = Wsrc + (size_t)(n0 + r0) * 2048 + c16 * 8;
    const uint32_t aSm0 = SW128((uint32_t)(r0 * 128 + c16 * 16));
    const uint32_t bSm0 = TILE_BYTES + SW128((uint32_t)(r0 * 128 + c16 * 16));

    uint32_t aRow[4];
#pragma unroll
    for (int i = 0; i < 4; i++)
        aRow[i] = (uint32_t)((wm * 64 + i * 16 + (lane & 15)) * 128 + (lane >> 4) * 16);
    uint32_t bRow[2];
#pragma unroll
    for (int g = 0; g < 2; g++)
        bRow[g] = (uint32_t)(TILE_BYTES +
                  (wn * 32 + g * 16 + ((lane >> 4) & 1) * 8 + (lane & 7)) * 128 +
                  ((lane >> 3) & 1) * 16);

    float acc[4][4][4];
#pragma unroll
    for (int i = 0; i < 4; i++)
#pragma unroll
        for (int j = 0; j < 4; j++)
#pragma unroll
            for (int r = 0; r < 4; r++) acc[i][j][r] = 0.f;

    auto issue = [&](int c) {
        const int seg = c >> 4;
        const int kc  = (c & 15) * 64;
        const int ka  = kc + ((seg == 2) ? 1024 : 0);
        const int kb  = kc + ((seg == 1) ? 1024 : 0);
        const uint32_t base = smem_base + (uint32_t)(c % NSTAGE) * BUF_BYTES;
#pragma unroll
        for (int i = 0; i < 4; i++)
            cp16(base + aSm0 + i * 4096u, aGm0 + ka + (size_t)i * 32 * 2048);
#pragma unroll
        for (int i = 0; i < 4; i++)
            cp16(base + bSm0 + i * 4096u, bGm0 + kb + (size_t)i * 32 * 2048);
        CP_COMMIT();
    };

    issue(0);
    issue(1);

    for (int c = 0; c < NCHUNK; c++) {
        if (c + 2 < NCHUNK) {
            CP_WAIT(1);
            __syncthreads();      // stage c visible; all warps done with stage c-1
            issue(c + 2);         // overwrites stage (c-1)%3 — safe after sync
        } else {
            CP_WAIT(0);
            __syncthreads();
        }

        const uint32_t base = smem_base + (uint32_t)(c % NSTAGE) * BUF_BYTES;
#pragma unroll
        for (int ks = 0; ks < 4; ks++) {
            const uint32_t kb32 = (uint32_t)(ks * 32);
            uint32_t af[4][4], bf[2][4];
#pragma unroll
            for (int i = 0; i < 4; i++)
                LDSM_X4(af[i], base + SW128(aRow[i] + kb32));
#pragma unroll
            for (int g = 0; g < 2; g++)
                LDSM_X4(bf[g], base + SW128(bRow[g] + kb32));
#pragma unroll
            for (int i = 0; i < 4; i++) {
#pragma unroll
                for (int j = 0; j < 4; j++) {
                    const uint32_t* bb = bf[j >> 1];
                    MMA16816(acc[i][j], af[i], bb[(j & 1) * 2], bb[(j & 1) * 2 + 1]);
                }
            }
        }
    }

    const int r4 = lane >> 2;
    const int c2 = (lane & 3) * 2;

    if (!QKV) {
        // Plain fp32 epilogue
#pragma unroll
        for (int i = 0; i < 4; i++) {
            const int mbase = m0 + wm * 64 + i * 16 + r4;
#pragma unroll
            for (int j = 0; j < 4; j++) {
                const int n = n0 + wn * 32 + j * 8 + c2;
#pragma unroll
                for (int rr = 0; rr < 2; rr++) {
                    const int m = mbase + rr * 8;
                    float2 val;
                    val.x = acc[i][j][rr * 2 + 0];
                    val.y = acc[i][j][rr * 2 + 1];
                    *(float2*)(out + (size_t)m * D_ + n) = val;
                }
            }
        }
        return;
    }

    // ---- Fused QKV epilogue: stage fp32 tile via ring smem, rope + split ----
    __syncthreads();              // all warps done with last LDSM reads
    float* sf = (float*)smc;      // reuse ring: 128 x 132 fp32 (67.5 KB)
#pragma unroll
    for (int i = 0; i < 4; i++) {
#pragma unroll
        for (int j = 0; j < 4; j++) {
            const int nl = wn * 32 + j * 8 + c2;
#pragma unroll
            for (int rr = 0; rr < 2; rr++) {
                const int ml = wm * 64 + i * 16 + rr * 8 + r4;
                sf[ml * 132 + nl]     = acc[i][j][rr * 2 + 0];
                sf[ml * 132 + nl + 1] = acc[i][j][rr * 2 + 1];
            }
        }
    }
    __syncthreads();

    __nv_bfloat16* dstbase = (zmode == 0) ? g_qc : (zmode == 1) ? g_kc : g_vc;

#pragma unroll
    for (int it = 0; it < 2; it++) {
        const int u    = tid + 256 * it;       // 512 units: 128 rows x 2 heads x 2 halves
        const int r    = u >> 2;
        const int hh   = (u >> 1) & 1;
        const int half = u & 1;
        const int c0   = half * 16;

        const int m = m0 + r;
        const int s = m & 511;
        const int bcur = m >> 9;
        const int hglob = (n0 >> 6) + hh;
        const size_t plane = (size_t)(bcur * H_ + hglob) * 2 * S_ * 64;

        const float* srow = sf + r * 132 + hh * 64;
        float x[32];
#pragma unroll
        for (int j2 = 0; j2 < 4; j2++) {
            *(float4*)&x[j2 * 4]      = *(const float4*)(srow + c0 + j2 * 4);
            *(float4*)&x[16 + j2 * 4] = *(const float4*)(srow + c0 + 32 + j2 * 4);
        }

        if (zmode != 2) {
            const float* tab = g_rope[s];
            const float sc = (zmode == 0) ? 0.125f : 1.0f;
#pragma unroll
            for (int j2 = 0; j2 < 16; j2++) {
                const float csv = tab[c0 + j2] * sc;
                const float snv = tab[c0 + j2 + 32] * sc;
                const float a = x[j2], b2v = x[16 + j2];
                x[j2]      = a * csv - b2v * snv;
                x[16 + j2] = b2v * csv + a * snv;
            }
        }
        prep_write(x, dstbase + plane, s, c0);
    }
}

__global__ void __launch_bounds__(256, 2) gemm_qkv()
{
    gemm_body<true>(nullptr, blockIdx.z);
}

__global__ void __launch_bounds__(256, 2) gemm_out(float* __restrict__ out)
{
    gemm_body<false>(out, 3);
}

// ---------------------------------------------------------------------------
// HMMA causal flash attention with prepped bf16 operands + cp.async ring.
// Block = (qb, h, b); 128 threads = 4 warps; warp w owns 16 query rows.
// smem: Q (QH 8KB | QL 8KB) then 3 KV stages of 32KB (KH|KL|VH|VL).
// 112 KB smem -> 2 CTAs/SM. Heavy blocks (large qb) launch first.
// ---------------------------------------------------------------------------
#define ATT_ST   16384
#define ATT_STB  32768
#define ATT_SMEM (ATT_ST + 3 * ATT_STB)   // 114688

// cp.async one 64x64 bf16 plane (8KB) into SW128-swizzled smem
__device__ __forceinline__ void cpa_plane(uint32_t dst, const __nv_bfloat16* __restrict__ src,
                                          int tid)
{
#pragma unroll
    for (int i = 0; i < 4; i++) {
        int u = tid + 128 * i;
        int r = u >> 3, ch = u & 7;
        cp16(dst + SW128((uint32_t)(r * 128 + ch * 16)), src + (size_t)r * 64 + ch * 8);
    }
}

__global__ void __launch_bounds__(128) attn_mma()
{
    extern __shared__ char sm[];
    const uint32_t sb = smem_u32(sm);

    const int tid  = threadIdx.x;
    const int lane = tid & 31;
    const int w    = tid >> 5;
    const int qb = (S_ / 64 - 1) - blockIdx.x;   // heavy blocks first
    const int h  = blockIdx.y;
    const int b  = blockIdx.z;
    const int q0 = qb * 64;
    const int bh = b * H_ + h;

    const size_t plane = (size_t)bh * 2 * S_ * 64;
    const size_t LO = (size_t)S_ * 64;
    const __nv_bfloat16* Qc = g_qc + plane;
    const __nv_bfloat16* Kc = g_kc + plane;
    const __nv_bfloat16* Vc = g_vc + plane;

    const int i7  = lane & 7;
    const int grp = lane >> 3;

    auto issue_kv = [&](int kb) {
        const uint32_t st = sb + ATT_ST + (uint32_t)(kb % 3) * ATT_STB;
        const int k0 = kb * 64;
        cpa_plane(st,         Kc + (size_t)k0 * 64,      tid);
        cpa_plane(st + 8192,  Kc + LO + (size_t)k0 * 64, tid);
        cpa_plane(st + 16384, Vc + (size_t)k0 * 64,      tid);
        cpa_plane(st + 24576, Vc + LO + (size_t)k0 * 64, tid);
        CP_COMMIT();
    };

    // group 0: Q + KV stage 0;  group 1: KV stage 1 (if needed)
    cpa_plane(sb,        Qc + (size_t)q0 * 64,      tid);
    cpa_plane(sb + 8192, Qc + LO + (size_t)q0 * 64, tid);
    {
        const uint32_t st = sb + ATT_ST;
        cpa_plane(st,         Kc,      tid);
        cpa_plane(st + 8192,  Kc + LO, tid);
        cpa_plane(st + 16384, Vc,      tid);
        cpa_plane(st + 24576, Vc + LO, tid);
        CP_COMMIT();
    }
    if (qb >= 1) issue_kv(1);

    uint32_t qh[4][4], ql[4][4];
    float mr0 = -1e30f, mr1 = -1e30f;
    float l0 = 0.f, l1 = 0.f;
    float O[8][4];
#pragma unroll
    for (int i = 0; i < 8; i++)
#pragma unroll
        for (int j = 0; j < 4; j++) O[i][j] = 0.f;

    for (int kb = 0; kb <= qb; kb++) {
        if (kb + 1 <= qb) { CP_WAIT(1); } else { CP_WAIT(0); }
        __syncthreads();
        if (kb + 2 <= qb) issue_kv(kb + 2);

        if (kb == 0) {
            // Q fragments (once)
            const int m0 = w * 16;
#pragma unroll
            for (int kc = 0; kc < 4; kc++) {
                const int row = m0 + (grp & 1) * 8 + i7;
                const uint32_t kbyte = (uint32_t)(kc * 32 + (grp >> 1) * 16);
                LDSM_X4(qh[kc], sb + SW128((uint32_t)(row * 128) + kbyte));
                LDSM_X4(ql[kc], sb + 8192 + SW128((uint32_t)(row * 128) + kbyte));
            }
        }

        const uint32_t st = sb + ATT_ST + (uint32_t)(kb % 3) * ATT_STB;
        const uint32_t KH = st, KL = st + 8192, VH = st + 16384, VL = st + 24576;

        // ---- Scores S[64q x 64k] per warp, 3 error-comp passes ----
        float S[8][4];
#pragma unroll
        for (int i = 0; i < 8; i++)
#pragma unroll
            for (int j = 0; j < 4; j++) S[i][j] = 0.f;

#pragma unroll
        for (int kc = 0; kc < 4; kc++) {
#pragma unroll
            for (int n2 = 0; n2 < 4; n2++) {
                const int row = n2 * 16 + (grp >> 1) * 8 + i7;
                const uint32_t kbyte = (uint32_t)(kc * 32 + (grp & 1) * 16);
                uint32_t bhf[4], blf[4];
                LDSM_X4(bhf, KH + SW128((uint32_t)(row * 128) + kbyte));
                LDSM_X4(blf, KL + SW128((uint32_t)(row * 128) + kbyte));
                MMA16816(S[n2 * 2],     qh[kc], bhf[0], bhf[1]);
                MMA16816(S[n2 * 2 + 1], qh[kc], bhf[2], bhf[3]);
                MMA16816(S[n2 * 2],     ql[kc], bhf[0], bhf[1]);
                MMA16816(S[n2 * 2 + 1], ql[kc], bhf[2], bhf[3]);
                MMA16816(S[n2 * 2],     qh[kc], blf[0], blf[1]);
                MMA16816(S[n2 * 2 + 1], qh[kc], blf[2], blf[3]);
            }
        }

        // ---- Causal mask (diagonal block only) ----
        if (kb == qb) {
            const int rloc0 = w * 16 + (lane >> 2);
            const int cbase = (lane & 3) * 2;
#pragma unroll
            for (int jt = 0; jt < 8; jt++) {
                const int c = jt * 8 + cbase;
                if (c     > rloc0)     S[jt][0] = -1e30f;
                if (c + 1 > rloc0)     S[jt][1] = -1e30f;
                if (c     > rloc0 + 8) S[jt][2] = -1e30f;
                if (c + 1 > rloc0 + 8) S[jt][3] = -1e30f;
            }
        }

        // ---- Online softmax ----
        float bm0 = -1e30f, bm1 = -1e30f;
#pragma unroll
        for (int jt = 0; jt < 8; jt++) {
            bm0 = fmaxf(bm0, fmaxf(S[jt][0], S[jt][1]));
            bm1 = fmaxf(bm1, fmaxf(S[jt][2], S[jt][3]));
        }
        bm0 = fmaxf(bm0, __shfl_xor_sync(0xFFFFFFFF, bm0, 1));
        bm0 = fmaxf(bm0, __shfl_xor_sync(0xFFFFFFFF, bm0, 2));
        bm1 = fmaxf(bm1, __shfl_xor_sync(0xFFFFFFFF, bm1, 1));
        bm1 = fmaxf(bm1, __shfl_xor_sync(0xFFFFFFFF, bm1, 2));

        const float mn0 = fmaxf(mr0, bm0);
        const float mn1 = fmaxf(mr1, bm1);
        const float corr0 = exp2f((mr0 - mn0) * LOG2E);
        const float corr1 = exp2f((mr1 - mn1) * LOG2E);
        mr0 = mn0; mr1 = mn1;
        l0 *= corr0; l1 *= corr1;

        float P[8][4];
#pragma unroll
        for (int jt = 0; jt < 8; jt++) {
            P[jt][0] = exp2f((S[jt][0] - mn0) * LOG2E);
            P[jt][1] = exp2f((S[jt][1] - mn0) * LOG2E);
            P[jt][2] = exp2f((S[jt][2] - mn1) * LOG2E);
            P[jt][3] = exp2f((S[jt][3] - mn1) * LOG2E);
            l0 += P[jt][0] + P[jt][1];
            l1 += P[jt][2] + P[jt][3];
        }
#pragma unroll
        for (int dt = 0; dt < 8; dt++) {
            O[dt][0] *= corr0; O[dt][1] *= corr0;
            O[dt][2] *= corr1; O[dt][3] *= corr1;
        }

        // ---- P A-fragments (hi/lo) from C-fragment layout ----
        uint32_t ph[4][4], pl[4][4];
#pragma unroll
        for (int kc = 0; kc < 4; kc++) {
            split2(P[2 * kc][0],     P[2 * kc][1],     ph[kc][0], pl[kc][0]);
            split2(P[2 * kc][2],     P[2 * kc][3],     ph[kc][1], pl[kc][1]);
            split2(P[2 * kc + 1][0], P[2 * kc + 1][1], ph[kc][2], pl[kc][2]);
            split2(P[2 * kc + 1][2], P[2 * kc + 1][3], ph[kc][3], pl[kc][3]);
        }

        // ---- PV, 3 error-comp passes (V via ldmatrix.trans) ----
#pragma unroll
        for (int kc = 0; kc < 4; kc++) {
#pragma unroll
            for (int d2 = 0; d2 < 4; d2++) {
                const int row = kc * 16 + (grp & 1) * 8 + i7;
                const uint32_t dbyte = (uint32_t)(d2 * 32 + (grp >> 1) * 16);
                uint32_t bhf[4], blf[4];
                LDSM_X4_T(bhf, VH + SW128((uint32_t)(row * 128) + dbyte));
                LDSM_X4_T(blf, VL + SW128((uint32_t)(row * 128) + dbyte));
                MMA16816(O[d2 * 2],     ph[kc], bhf[0], bhf[1]);
                MMA16816(O[d2 * 2 + 1], ph[kc], bhf[2], bhf[3]);
                MMA16816(O[d2 * 2],     pl[kc], bhf[0], bhf[1]);
                MMA16816(O[d2 * 2 + 1], pl[kc], bhf[2], bhf[3]);
                MMA16816(O[d2 * 2],     ph[kc], blf[0], blf[1]);
                MMA16816(O[d2 * 2 + 1], ph[kc], blf[2], blf[3]);
            }
        }
    }

    // ---- Final l reduction + normalized bf16 hi/lo write to g_xc ----
    l0 += __shfl_xor_sync(0xFFFFFFFF, l0, 1);
    l0 += __shfl_xor_sync(0xFFFFFFFF, l0, 2);
    l1 += __shfl_xor_sync(0xFFFFFFFF, l1, 1);
    l1 += __shfl_xor_sync(0xFFFFFFFF, l1, 2);
    const float inv0 = 1.0f / l0;
    const float inv1 = 1.0f / l1;

    const int rA = q0 + w * 16 + (lane >> 2);
    const int rB = rA + 8;
    const size_t tA = ((size_t)(b * S_ + rA)) * 2048;
    const size_t tB = ((size_t)(b * S_ + rB)) * 2048;
    const int colbase = h * 64 + (lane & 3) * 2;

#pragma unroll
    for (int dt = 0; dt < 8; dt++) {
        const int col = colbase + dt * 8;
        uint32_t hi, lo;
        split2(O[dt][0] * inv0, O[dt][1] * inv0, hi, lo);
        *(uint32_t*)&g_xc[tA + col]        = hi;
        *(uint32_t*)&g_xc[tA + 1024 + col] = lo;
        split2(O[dt][2] * inv1, O[dt][3] * inv1, hi, lo);
        *(uint32_t*)&g_xc[tB + col]        = hi;
        *(uint32_t*)&g_xc[tB + 1024 + col] = lo;
    }
}

// ---------------------------------------------------------------------------
extern "C" void kernel_launch(void* const* d_in, const int* in_sizes, int n_in,
                              void* d_out, int out_size)
{
    const float* x  = (const float*)d_in[0];
    const float* Wq = (const float*)d_in[1];
    const float* Wk = (const float*)d_in[2];
    const float* Wv = (const float*)d_in[3];
    const float* Wo = (const float*)d_in[4];
    float* out = (float*)d_out;

    cudaFuncSetAttribute(gemm_qkv, cudaFuncAttributeMaxDynamicSharedMemorySize, GEMM_SMEM);
    cudaFuncSetAttribute(gemm_out, cudaFuncAttributeMaxDynamicSharedMemorySize, GEMM_SMEM);
    cudaFuncSetAttribute(attn_mma, cudaFuncAttributeMaxDynamicSharedMemorySize, ATT_SMEM);

    // One merged prep launch: x-convert | weight-converts | rope table
    prep_inputs<<<6208, 256>>>(x, Wq, Wk, Wv, Wo);

    // Merged QKV projections with fused RoPE + bf16 split epilogue
    gemm_qkv<<<dim3(D_ / 128, TOK / 128, 3), 256, GEMM_SMEM>>>();

    attn_mma<<<dim3(S_ / 64, H_, B_), 128, ATT_SMEM>>>();

    gemm_out<<<dim3(D_ / 128, TOK / 128), 256, GEMM_SMEM>>>(out);
}

// round 14
// speedup vs baseline: 1.0598x; 1.0296x over previous
#include <cuda_runtime.h>
#include <cuda_bf16.h>
#include <math.h>
#include <stdint.h>

// Problem constants
#define B_  16
#define S_  512
#define D_  1024
#define H_  16
#define HD_ 64
#define TOK (B_ * S_)            // 8192 tokens

// Scratch (device globals; no dynamic allocation allowed)
__device__ float g_rope[S_][64];              // [s][0:32)=cos, [32:64)=sin

// bf16 hi|lo operands: A operand [TOK, 2048] (cols 0-1023 hi, 1024-2047 lo)
__device__ __nv_bfloat16 g_xc[(size_t)TOK * 2048];
// weights hi|lo: 4 x [1024, 2048]
__device__ __nv_bfloat16 g_wc[4][(size_t)D_ * 2048];
// prepped attention operands: [bh][plane(hi/lo)][S][64] bf16
__device__ __nv_bfloat16 g_qc[(size_t)B_ * H_ * 2 * S_ * 64];
__device__ __nv_bfloat16 g_kc[(size_t)B_ * H_ * 2 * S_ * 64];
__device__ __nv_bfloat16 g_vc[(size_t)B_ * H_ * 2 * S_ * 64];

#define LOG2E 1.4426950408889634f

// ---------------------------------------------------------------------------
// Helpers (family-portable PTX only: ldmatrix / mma.sync / cp.async)
// ---------------------------------------------------------------------------
__device__ __forceinline__ uint32_t smem_u32(const void* p) {
    uint32_t a;
    asm("{ .reg .u64 t; cvta.to.shared.u64 t, %1; cvt.u32.u64 %0, t; }"
        : "=r"(a) : "l"(p));
    return a;
}

#define SW128(off) ((off) ^ (((off) >> 3) & 0x70))

__device__ __forceinline__ void cp16(uint32_t s, const void* g) {
    asm volatile("cp.async.cg.shared.global [%0], [%1], 16;" :: "r"(s), "l"(g));
}
#define CP_COMMIT() asm volatile("cp.async.commit_group;" ::: "memory")
#define CP_WAIT(n)  asm volatile("cp.async.wait_group %0;" :: "n"(n) : "memory")

#define LDSM_X4(r, addr) \
    asm volatile("ldmatrix.sync.aligned.m8n8.x4.shared.b16 {%0,%1,%2,%3}, [%4];" \
        : "=r"((r)[0]), "=r"((r)[1]), "=r"((r)[2]), "=r"((r)[3]) : "r"(addr))

#define LDSM_X4_T(r, addr) \
    asm volatile("ldmatrix.sync.aligned.m8n8.x4.trans.shared.b16 {%0,%1,%2,%3}, [%4];" \
        : "=r"((r)[0]), "=r"((r)[1]), "=r"((r)[2]), "=r"((r)[3]) : "r"(addr))

#define MMA16816(d, a, b0, b1) \
    asm volatile("mma.sync.aligned.m16n8k16.row.col.f32.bf16.bf16.f32 " \
        "{%0,%1,%2,%3}, {%4,%5,%6,%7}, {%8,%9}, {%0,%1,%2,%3};" \
        : "+f"((d)[0]), "+f"((d)[1]), "+f"((d)[2]), "+f"((d)[3]) \
        : "r"((a)[0]), "r"((a)[1]), "r"((a)[2]), "r"((a)[3]), "r"(b0), "r"(b1))

// Split a pair of floats into packed bf16 hi + bf16 lo (error compensation)
__device__ __forceinline__ void split2(float a, float b, uint32_t& hi, uint32_t& lo) {
    __nv_bfloat16 ah = __float2bfloat16_rn(a);
    __nv_bfloat16 bh = __float2bfloat16_rn(b);
    float ar = a - __bfloat162float(ah);
    float br = b - __bfloat162float(bh);
    __nv_bfloat162 hp; hp.x = ah; hp.y = bh;
    __nv_bfloat162 lp; lp.x = __float2bfloat16_rn(ar); lp.y = __float2bfloat16_rn(br);
    hi = *(uint32_t*)&hp;
    lo = *(uint32_t*)&lp;
}

// ---------------------------------------------------------------------------
// Merged input prep: convert x (blocks 0..4095), convert weights
// (blocks 4096..6143), rope table (blocks 6144..6207). One launch.
// ---------------------------------------------------------------------------
__device__ __forceinline__ void conv_row_body(const float* __restrict__ s,
                                              __nv_bfloat16* __restrict__ dst,
                                              int row, int c8)
{
    float4 v0 = *(const float4*)(s);
    float4 v1 = *(const float4*)(s + 4);
    float vs[8] = {v0.x, v0.y, v0.z, v0.w, v1.x, v1.y, v1.z, v1.w};

    uint32_t hw[4], lw[4];
#pragma unroll
    for (int j = 0; j < 4; j++) split2(vs[2 * j], vs[2 * j + 1], hw[j], lw[j]);

    uint4* dh = (uint4*)(dst + (size_t)row * 2048 + c8);
    uint4* dl = (uint4*)(dst + (size_t)row * 2048 + 1024 + c8);
    *dh = make_uint4(hw[0], hw[1], hw[2], hw[3]);
    *dl = make_uint4(lw[0], lw[1], lw[2], lw[3]);
}

__global__ void prep_inputs(const float* __restrict__ x,
                            const float* __restrict__ w0, const float* __restrict__ w1,
                            const float* __restrict__ w2, const float* __restrict__ w3)
{
    const int blk = blockIdx.x;
    const int tid = threadIdx.x;

    if (blk < 4096) {
        // convert x -> g_xc
        int i = blk * 256 + tid;
        int row = i >> 7;
        int c8 = (i & 127) * 8;
        conv_row_body(x + (size_t)row * 1024 + c8, g_xc, row, c8);
    } else if (blk < 6144) {
        // convert weights -> g_wc
        int wb = blk - 4096;
        int which = wb >> 9;              // 0..3
        int i = (wb & 511) * 256 + tid;
        int row = i >> 7;
        int c8 = (i & 127) * 8;
        const float* src = (which == 0) ? w0 : (which == 1) ? w1
                         : (which == 2) ? w2 : w3;
        conv_row_body(src + (size_t)row * 1024 + c8, g_wc[which], row, c8);
    } else {
        // rope table
        int t = (blk - 6144) * 256 + tid;   // 512*32
        int d = t & 31;
        int s = t >> 5;
        float inv = expf(-(float)d * (9.210340371976184f / 32.0f));
        float ang = (float)s * inv;
        float sn, cs;
        sincosf(ang, &sn, &cs);
        g_rope[s][d] = cs;
        g_rope[s][d + 32] = sn;
    }
}

// ---------------------------------------------------------------------------
// bf16 hi/lo plane write for attention operands (x[0..15]=cols c0..,
// x[16..31]=cols c0+32..), dst layout [plane][S][64].
// ---------------------------------------------------------------------------
__device__ __forceinline__ void prep_write(const float* __restrict__ x,
                                           __nv_bfloat16* __restrict__ basehi,
                                           int s, int c0)
{
    uint32_t hi[16], lo[16];
#pragma unroll
    for (int p = 0; p < 8; p++)  split2(x[2 * p], x[2 * p + 1], hi[p], lo[p]);
#pragma unroll
    for (int p = 0; p < 8; p++)  split2(x[16 + 2 * p], x[17 + 2 * p], hi[8 + p], lo[8 + p]);

    __nv_bfloat16* ph = basehi + (size_t)s * 64;
    __nv_bfloat16* pl = basehi + (size_t)S_ * 64 + (size_t)s * 64;
    *(uint4*)(ph + c0)      = make_uint4(hi[0], hi[1], hi[2], hi[3]);
    *(uint4*)(ph + c0 + 8)  = make_uint4(hi[4], hi[5], hi[6], hi[7]);
    *(uint4*)(ph + c0 + 32) = make_uint4(hi[8], hi[9], hi[10], hi[11]);
    *(uint4*)(ph + c0 + 40) = make_uint4(hi[12], hi[13], hi[14], hi[15]);
    *(uint4*)(pl + c0)      = make_uint4(lo[0], lo[1], lo[2], lo[3]);
    *(uint4*)(pl + c0 + 8)  = make_uint4(lo[4], lo[5], lo[6], lo[7]);
    *(uint4*)(pl + c0 + 32) = make_uint4(lo[8], lo[9], lo[10], lo[11]);
    *(uint4*)(pl + c0 + 40) = make_uint4(lo[12], lo[13], lo[14], lo[15]);
}

// ---------------------------------------------------------------------------
// HMMA GEMM: C[m,n] = sum_k A[m,k]*W[n,k], bf16x3 split (K' = 3072).
// CTA 128x128 (8 warps, warp tile 64x32), 3-stage cp.async ring, SW128,
// single __syncthreads per chunk, 2 CTAs/SM (<=128 regs).
// QKV variant: fused RoPE + bf16 hi/lo split epilogue -> g_qc/g_kc/g_vc.
// OUT variant: Wo, plain fp32 write.
// ---------------------------------------------------------------------------
#define NCHUNK 48                 // 3 segments x 16 chunks of K=64
#define TILE_BYTES 16384          // 128 rows x 128 bytes
#define BUF_BYTES  (2 * TILE_BYTES)
#define NSTAGE 3
#define GEMM_SMEM  (NSTAGE * BUF_BYTES)   // 98304

template<bool QKV>
__device__ __forceinline__ void gemm_body(float* __restrict__ out, int zmode)
{
    extern __shared__ char smc[];
    const uint32_t smem_base = smem_u32(smc);
    const int tid  = threadIdx.x;
    const int wid  = tid >> 5;
    const int lane = tid & 31;
    const int wm   = wid >> 2;      // 0..1
    const int wn   = wid & 3;       // 0..3

    const int n0 = blockIdx.x * 128;
    const int m0 = blockIdx.y * 128;

    const __nv_bfloat16* __restrict__ Wsrc = g_wc[QKV ? zmode : 3];

    const int r0  = tid >> 3;
    const int c16 = tid & 7;
    const __nv_bfloat16* aGm0 = g_xc + (size_t)(m0 + r0) * 2048 + c16 * 8;
    const __nv_bfloat16* bGm0 = Wsrc + (size_t)(n0 + r0) * 2048 + c16 * 8;
    const uint32_t aSm0 = SW128((uint32_t)(r0 * 128 + c16 * 16));
    const uint32_t bSm0 = TILE_BYTES + SW128((uint32_t)(r0 * 128 + c16 * 16));

    uint32_t aRow[4];
#pragma unroll
    for (int i = 0; i < 4; i++)
        aRow[i] = (uint32_t)((wm * 64 + i * 16 + (lane & 15)) * 128 + (lane >> 4) * 16);
    uint32_t bRow[2];
#pragma unroll
    for (int g = 0; g < 2; g++)
        bRow[g] = (uint32_t)(TILE_BYTES +
                  (wn * 32 + g * 16 + ((lane >> 4) & 1) * 8 + (lane & 7)) * 128 +
                  ((lane >> 3) & 1) * 16);

    float acc[4][4][4];
#pragma unroll
    for (int i = 0; i < 4; i++)
#pragma unroll
        for (int j = 0; j < 4; j++)
#pragma unroll
            for (int r = 0; r < 4; r++) acc[i][j][r] = 0.f;

    auto issue = [&](int c) {
        const int seg = c >> 4;
        const int kc  = (c & 15) * 64;
        const int ka  = kc + ((seg == 2) ? 1024 : 0);
        const int kb  = kc + ((seg == 1) ? 1024 : 0);
        const uint32_t base = smem_base + (uint32_t)(c % NSTAGE) * BUF_BYTES;
#pragma unroll
        for (int i = 0; i < 4; i++)
            cp16(base + aSm0 + i * 4096u, aGm0 + ka + (size_t)i * 32 * 2048);
#pragma unroll
        for (int i = 0; i < 4; i++)
            cp16(base + bSm0 + i * 4096u, bGm0 + kb + (size_t)i * 32 * 2048);
        CP_COMMIT();
    };

    issue(0);
    issue(1);

    for (int c = 0; c < NCHUNK; c++) {
        if (c + 2 < NCHUNK) {
            CP_WAIT(1);
            __syncthreads();      // stage c visible; all warps done with stage c-1
            issue(c + 2);         // overwrites stage (c-1)%3 — safe after sync
        } else {
            CP_WAIT(0);
            __syncthreads();
        }

        const uint32_t base = smem_base + (uint32_t)(c % NSTAGE) * BUF_BYTES;
#pragma unroll
        for (int ks = 0; ks < 4; ks++) {
            const uint32_t kb32 = (uint32_t)(ks * 32);
            uint32_t af[4][4], bf[2][4];
#pragma unroll
            for (int i = 0; i < 4; i++)
                LDSM_X4(af[i], base + SW128(aRow[i] + kb32));
#pragma unroll
            for (int g = 0; g < 2; g++)
                LDSM_X4(bf[g], base + SW128(bRow[g] + kb32));
#pragma unroll
            for (int i = 0; i < 4; i++) {
#pragma unroll
                for (int j = 0; j < 4; j++) {
                    const uint32_t* bb = bf[j >> 1];
                    MMA16816(acc[i][j], af[i], bb[(j & 1) * 2], bb[(j & 1) * 2 + 1]);
                }
            }
        }
    }

    const int r4 = lane >> 2;
    const int c2 = (lane & 3) * 2;

    if (!QKV) {
        // Plain fp32 epilogue
#pragma unroll
        for (int i = 0; i < 4; i++) {
            const int mbase = m0 + wm * 64 + i * 16 + r4;
#pragma unroll
            for (int j = 0; j < 4; j++) {
                const int n = n0 + wn * 32 + j * 8 + c2;
#pragma unroll
                for (int rr = 0; rr < 2; rr++) {
                    const int m = mbase + rr * 8;
                    float2 val;
                    val.x = acc[i][j][rr * 2 + 0];
                    val.y = acc[i][j][rr * 2 + 1];
                    *(float2*)(out + (size_t)m * D_ + n) = val;
                }
            }
        }
        return;
    }

    // ---- Fused QKV epilogue: stage fp32 tile via ring smem, rope + split ----
    __syncthreads();              // all warps done with last LDSM reads
    float* sf = (float*)smc;      // reuse ring: 128 x 132 fp32 (67.5 KB)
#pragma unroll
    for (int i = 0; i < 4; i++) {
#pragma unroll
        for (int j = 0; j < 4; j++) {
            const int nl = wn * 32 + j * 8 + c2;
#pragma unroll
            for (int rr = 0; rr < 2; rr++) {
                const int ml = wm * 64 + i * 16 + rr * 8 + r4;
                sf[ml * 132 + nl]     = acc[i][j][rr * 2 + 0];
                sf[ml * 132 + nl + 1] = acc[i][j][rr * 2 + 1];
            }
        }
    }
    __syncthreads();

    __nv_bfloat16* dstbase = (zmode == 0) ? g_qc : (zmode == 1) ? g_kc : g_vc;

#pragma unroll
    for (int it = 0; it < 2; it++) {
        const int u    = tid + 256 * it;       // 512 units: 128 rows x 2 heads x 2 halves
        const int r    = u >> 2;
        const int hh   = (u >> 1) & 1;
        const int half = u & 1;
        const int c0   = half * 16;

        const int m = m0 + r;
        const int s = m & 511;
        const int bcur = m >> 9;
        const int hglob = (n0 >> 6) + hh;
        const size_t plane = (size_t)(bcur * H_ + hglob) * 2 * S_ * 64;

        const float* srow = sf + r * 132 + hh * 64;
        float x[32];
#pragma unroll
        for (int j2 = 0; j2 < 4; j2++) {
            *(float4*)&x[j2 * 4]      = *(const float4*)(srow + c0 + j2 * 4);
            *(float4*)&x[16 + j2 * 4] = *(const float4*)(srow + c0 + 32 + j2 * 4);
        }

        if (zmode != 2) {
            const float* tab = g_rope[s];
            const float sc = (zmode == 0) ? 0.125f : 1.0f;
#pragma unroll
            for (int j2 = 0; j2 < 16; j2++) {
                const float csv = tab[c0 + j2] * sc;
                const float snv = tab[c0 + j2 + 32] * sc;
                const float a = x[j2], b2v = x[16 + j2];
                x[j2]      = a * csv - b2v * snv;
                x[16 + j2] = b2v * csv + a * snv;
            }
        }
        prep_write(x, dstbase + plane, s, c0);
    }
}

__global__ void __launch_bounds__(256, 2) gemm_qkv()
{
    gemm_body<true>(nullptr, blockIdx.z);
}

__global__ void __launch_bounds__(256, 2) gemm_out(float* __restrict__ out)
{
    gemm_body<false>(out, 3);
}

// ---------------------------------------------------------------------------
// HMMA causal flash attention. Block = (qb, h, b); 128 threads = 4 warps;
// warp w owns 16 query rows. Q fragments loaded DIRECTLY from gmem (no Q
// smem). 2-stage KV ring (2 x 32KB = 64KB smem) -> 3 CTAs/SM, 12 warps/SM.
// ---------------------------------------------------------------------------
#define ATT_STB  32768
#define ATT_SMEM (2 * ATT_STB)   // 65536

// cp.async one 64x64 bf16 plane (8KB) into SW128-swizzled smem
__device__ __forceinline__ void cpa_plane(uint32_t dst, const __nv_bfloat16* __restrict__ src,
                                          int tid)
{
#pragma unroll
    for (int i = 0; i < 4; i++) {
        int u = tid + 128 * i;
        int r = u >> 3, ch = u & 7;
        cp16(dst + SW128((uint32_t)(r * 128 + ch * 16)), src + (size_t)r * 64 + ch * 8);
    }
}

__global__ void __launch_bounds__(128, 3) attn_mma()
{
    extern __shared__ char sm[];
    const uint32_t sb = smem_u32(sm);

    const int tid  = threadIdx.x;
    const int lane = tid & 31;
    const int w    = tid >> 5;
    const int qb = blockIdx.x;
    const int h  = blockIdx.y;
    const int b  = blockIdx.z;
    const int q0 = qb * 64;
    const int bh = b * H_ + h;

    const size_t plane = (size_t)bh * 2 * S_ * 64;
    const size_t LO = (size_t)S_ * 64;
    const __nv_bfloat16* Qc = g_qc + plane;
    const __nv_bfloat16* Kc = g_kc + plane;
    const __nv_bfloat16* Vc = g_vc + plane;

    const int i7  = lane & 7;
    const int grp = lane >> 3;

    auto issue_kv = [&](int kb) {
        const uint32_t st = sb + (uint32_t)(kb & 1) * ATT_STB;
        const int k0 = kb * 64;
        cpa_plane(st,         Kc + (size_t)k0 * 64,      tid);
        cpa_plane(st + 8192,  Kc + LO + (size_t)k0 * 64, tid);
        cpa_plane(st + 16384, Vc + (size_t)k0 * 64,      tid);
        cpa_plane(st + 24576, Vc + LO + (size_t)k0 * 64, tid);
        CP_COMMIT();
    };

    issue_kv(0);
    if (qb >= 1) issue_kv(1);

    // ---- Q fragments straight from gmem (mma A-layout: pairs at
    //      (rowA/rowB, kc*16 + (lane&3)*2 [+8]); values bit-identical to the
    //      previous smem+ldmatrix path. ~16KB per CTA, L2-hot. ----
    uint32_t qh[4][4], ql[4][4];
    {
        const int rowA = q0 + w * 16 + (lane >> 2);
        const int rowB = rowA + 8;
        const int cc = (lane & 3) * 2;
#pragma unroll
        for (int kc = 0; kc < 4; kc++) {
            const int col = kc * 16 + cc;
            qh[kc][0] = *(const uint32_t*)&Qc[(size_t)rowA * 64 + col];
            qh[kc][1] = *(const uint32_t*)&Qc[(size_t)rowB * 64 + col];
            qh[kc][2] = *(const uint32_t*)&Qc[(size_t)rowA * 64 + col + 8];
            qh[kc][3] = *(const uint32_t*)&Qc[(size_t)rowB * 64 + col + 8];
            ql[kc][0] = *(const uint32_t*)&Qc[LO + (size_t)rowA * 64 + col];
            ql[kc][1] = *(const uint32_t*)&Qc[LO + (size_t)rowB * 64 + col];
            ql[kc][2] = *(const uint32_t*)&Qc[LO + (size_t)rowA * 64 + col + 8];
            ql[kc][3] = *(const uint32_t*)&Qc[LO + (size_t)rowB * 64 + col + 8];
        }
    }

    float mr0 = -1e30f, mr1 = -1e30f;
    float l0 = 0.f, l1 = 0.f;
    float O[8][4];
#pragma unroll
    for (int i = 0; i < 8; i++)
#pragma unroll
        for (int j = 0; j < 4; j++) O[i][j] = 0.f;

    for (int kb = 0; kb <= qb; kb++) {
        if (kb + 1 <= qb) { CP_WAIT(1); } else { CP_WAIT(0); }
        __syncthreads();          // stage kb ready for all warps

        const uint32_t st = sb + (uint32_t)(kb & 1) * ATT_STB;
        const uint32_t KH = st, KL = st + 8192, VH = st + 16384, VL = st + 24576;

        // ---- Scores S[64q x 64k] per warp, 3 error-comp passes ----
        float S[8][4];
#pragma unroll
        for (int i = 0; i < 8; i++)
#pragma unroll
            for (int j = 0; j < 4; j++) S[i][j] = 0.f;

#pragma unroll
        for (int kc = 0; kc < 4; kc++) {
#pragma unroll
            for (int n2 = 0; n2 < 4; n2++) {
                const int row = n2 * 16 + (grp >> 1) * 8 + i7;
                const uint32_t kbyte = (uint32_t)(kc * 32 + (grp & 1) * 16);
                uint32_t bhf[4], blf[4];
                LDSM_X4(bhf, KH + SW128((uint32_t)(row * 128) + kbyte));
                LDSM_X4(blf, KL + SW128((uint32_t)(row * 128) + kbyte));
                MMA16816(S[n2 * 2],     qh[kc], bhf[0], bhf[1]);
                MMA16816(S[n2 * 2 + 1], qh[kc], bhf[2], bhf[3]);
                MMA16816(S[n2 * 2],     ql[kc], bhf[0], bhf[1]);
                MMA16816(S[n2 * 2 + 1], ql[kc], bhf[2], bhf[3]);
                MMA16816(S[n2 * 2],     qh[kc], blf[0], blf[1]);
                MMA16816(S[n2 * 2 + 1], qh[kc], blf[2], blf[3]);
            }
        }

        // ---- Causal mask (diagonal block only) ----
        if (kb == qb) {
            const int rloc0 = w * 16 + (lane >> 2);
            const int cbase = (lane & 3) * 2;
#pragma unroll
            for (int jt = 0; jt < 8; jt++) {
                const int c = jt * 8 + cbase;
                if (c     > rloc0)     S[jt][0] = -1e30f;
                if (c + 1 > rloc0)     S[jt][1] = -1e30f;
                if (c     > rloc0 + 8) S[jt][2] = -1e30f;
                if (c + 1 > rloc0 + 8) S[jt][3] = -1e30f;
            }
        }

        // ---- Online softmax ----
        float bm0 = -1e30f, bm1 = -1e30f;
#pragma unroll
        for (int jt = 0; jt < 8; jt++) {
            bm0 = fmaxf(bm0, fmaxf(S[jt][0], S[jt][1]));
            bm1 = fmaxf(bm1, fmaxf(S[jt][2], S[jt][3]));
        }
        bm0 = fmaxf(bm0, __shfl_xor_sync(0xFFFFFFFF, bm0, 1));
        bm0 = fmaxf(bm0, __shfl_xor_sync(0xFFFFFFFF, bm0, 2));
        bm1 = fmaxf(bm1, __shfl_xor_sync(0xFFFFFFFF, bm1, 1));
        bm1 = fmaxf(bm1, __shfl_xor_sync(0xFFFFFFFF, bm1, 2));

        const float mn0 = fmaxf(mr0, bm0);
        const float mn1 = fmaxf(mr1, bm1);
        const float corr0 = exp2f((mr0 - mn0) * LOG2E);
        const float corr1 = exp2f((mr1 - mn1) * LOG2E);
        mr0 = mn0; mr1 = mn1;
        l0 *= corr0; l1 *= corr1;

        float P[8][4];
#pragma unroll
        for (int jt = 0; jt < 8; jt++) {
            P[jt][0] = exp2f((S[jt][0] - mn0) * LOG2E);
            P[jt][1] = exp2f((S[jt][1] - mn0) * LOG2E);
            P[jt][2] = exp2f((S[jt][2] - mn1) * LOG2E);
            P[jt][3] = exp2f((S[jt][3] - mn1) * LOG2E);
            l0 += P[jt][0] + P[jt][1];
            l1 += P[jt][2] + P[jt][3];
        }
#pragma unroll
        for (int dt = 0; dt < 8; dt++) {
            O[dt][0] *= corr0; O[dt][1] *= corr0;
            O[dt][2] *= corr1; O[dt][3] *= corr1;
        }

        // ---- P A-fragments (hi/lo) from C-fragment layout ----
        uint32_t ph[4][4], pl[4][4];
#pragma unroll
        for (int kc = 0; kc < 4; kc++) {
            split2(P[2 * kc][0],     P[2 * kc][1],     ph[kc][0], pl[kc][0]);
            split2(P[2 * kc][2],     P[2 * kc][3],     ph[kc][1], pl[kc][1]);
            split2(P[2 * kc + 1][0], P[2 * kc + 1][1], ph[kc][2], pl[kc][2]);
            split2(P[2 * kc + 1][2], P[2 * kc + 1][3], ph[kc][3], pl[kc][3]);
        }

        // ---- PV, 3 error-comp passes (V via ldmatrix.trans) ----
#pragma unroll
        for (int kc = 0; kc < 4; kc++) {
#pragma unroll
            for (int d2 = 0; d2 < 4; d2++) {
                const int row = kc * 16 + (grp & 1) * 8 + i7;
                const uint32_t dbyte = (uint32_t)(d2 * 32 + (grp >> 1) * 16);
                uint32_t bhf[4], blf[4];
                LDSM_X4_T(bhf, VH + SW128((uint32_t)(row * 128) + dbyte));
                LDSM_X4_T(blf, VL + SW128((uint32_t)(row * 128) + dbyte));
                MMA16816(O[d2 * 2],     ph[kc], bhf[0], bhf[1]);
                MMA16816(O[d2 * 2 + 1], ph[kc], bhf[2], bhf[3]);
                MMA16816(O[d2 * 2],     pl[kc], bhf[0], bhf[1]);
                MMA16816(O[d2 * 2 + 1], pl[kc], bhf[2], bhf[3]);
                MMA16816(O[d2 * 2],     ph[kc], blf[0], blf[1]);
                MMA16816(O[d2 * 2 + 1], ph[kc], blf[2], blf[3]);
            }
        }

        // Re-issue into the buffer we just finished reading (2-stage ring).
        if (kb + 2 <= qb) {
            __syncthreads();      // all warps done reading stage kb
            issue_kv(kb + 2);
        }
    }

    // ---- Final l reduction + normalized bf16 hi/lo write to g_xc ----
    l0 += __shfl_xor_sync(0xFFFFFFFF, l0, 1);
    l0 += __shfl_xor_sync(0xFFFFFFFF, l0, 2);
    l1 += __shfl_xor_sync(0xFFFFFFFF, l1, 1);
    l1 += __shfl_xor_sync(0xFFFFFFFF, l1, 2);
    const float inv0 = 1.0f / l0;
    const float inv1 = 1.0f / l1;

    const int rA = q0 + w * 16 + (lane >> 2);
    const int rB = rA + 8;
    const size_t tA = ((size_t)(b * S_ + rA)) * 2048;
    const size_t tB = ((size_t)(b * S_ + rB)) * 2048;
    const int colbase = h * 64 + (lane & 3) * 2;

#pragma unroll
    for (int dt = 0; dt < 8; dt++) {
        const int col = colbase + dt * 8;
        uint32_t hi, lo;
        split2(O[dt][0] * inv0, O[dt][1] * inv0, hi, lo);
        *(uint32_t*)&g_xc[tA + col]        = hi;
        *(uint32_t*)&g_xc[tA + 1024 + col] = lo;
        split2(O[dt][2] * inv1, O[dt][3] * inv1, hi, lo);
        *(uint32_t*)&g_xc[tB + col]        = hi;
        *(uint32_t*)&g_xc[tB + 1024 + col] = lo;
    }
}

// ---------------------------------------------------------------------------
extern "C" void kernel_launch(void* const* d_in, const int* in_sizes, int n_in,
                              void* d_out, int out_size)
{
    const float* x  = (const float*)d_in[0];
    const float* Wq = (const float*)d_in[1];
    const float* Wk = (const float*)d_in[2];
    const float* Wv = (const float*)d_in[3];
    const float* Wo = (const float*)d_in[4];
    float* out = (float*)d_out;

    cudaFuncSetAttribute(gemm_qkv, cudaFuncAttributeMaxDynamicSharedMemorySize, GEMM_SMEM);
    cudaFuncSetAttribute(gemm_out, cudaFuncAttributeMaxDynamicSharedMemorySize, GEMM_SMEM);
    cudaFuncSetAttribute(attn_mma, cudaFuncAttributeMaxDynamicSharedMemorySize, ATT_SMEM);

    // One merged prep launch: x-convert | weight-converts | rope table
    prep_inputs<<<6208, 256>>>(x, Wq, Wk, Wv, Wo);

    // Merged QKV projections with fused RoPE + bf16 split epilogue
    gemm_qkv<<<dim3(D_ / 128, TOK / 128, 3), 256, GEMM_SMEM>>>();

    attn_mma<<<dim3(S_ / 64, H_, B_), 128, ATT_SMEM>>>();

    gemm_out<<<dim3(D_ / 128, TOK / 128), 256, GEMM_SMEM>>>(out);
}

// round 15
// speedup vs baseline: 1.4051x; 1.3259x over previous
#include <cuda_runtime.h>
#include <cuda_bf16.h>
#include <cuda_fp16.h>
#include <math.h>
#include <stdint.h>

// Problem constants
#define B_  16
#define S_  512
#define D_  1024
#define H_  16
#define HD_ 64
#define TOK (B_ * S_)            // 8192 tokens

// Scratch (device globals; no dynamic allocation allowed)
__device__ float g_rope[S_][64];              // [s][0:32)=cos, [32:64)=sin

// fp16 hi|lo activations: [TOK, 2048] (cols 0-1023 hi, 1024-2047 lo)
__device__ __half g_xc[(size_t)TOK * 2048];
// weights: single fp16 plane, 4 x [1024, 1024]
__device__ __half g_wc[4][(size_t)D_ * 1024];
// prepped attention operands (bf16, 3-pass path): [bh][plane(hi/lo)][S][64]
__device__ __nv_bfloat16 g_qc[(size_t)B_ * H_ * 2 * S_ * 64];
__device__ __nv_bfloat16 g_kc[(size_t)B_ * H_ * 2 * S_ * 64];
__device__ __nv_bfloat16 g_vc[(size_t)B_ * H_ * 2 * S_ * 64];

#define LOG2E 1.4426950408889634f

// ---------------------------------------------------------------------------
// Helpers (family-portable PTX only: ldmatrix / mma.sync / cp.async)
// ---------------------------------------------------------------------------
__device__ __forceinline__ uint32_t smem_u32(const void* p) {
    uint32_t a;
    asm("{ .reg .u64 t; cvta.to.shared.u64 t, %1; cvt.u32.u64 %0, t; }"
        : "=r"(a) : "l"(p));
    return a;
}

#define SW128(off) ((off) ^ (((off) >> 3) & 0x70))

__device__ __forceinline__ void cp16(uint32_t s, const void* g) {
    asm volatile("cp.async.cg.shared.global [%0], [%1], 16;" :: "r"(s), "l"(g));
}
#define CP_COMMIT() asm volatile("cp.async.commit_group;" ::: "memory")
#define CP_WAIT(n)  asm volatile("cp.async.wait_group %0;" :: "n"(n) : "memory")

#define LDSM_X4(r, addr) \
    asm volatile("ldmatrix.sync.aligned.m8n8.x4.shared.b16 {%0,%1,%2,%3}, [%4];" \
        : "=r"((r)[0]), "=r"((r)[1]), "=r"((r)[2]), "=r"((r)[3]) : "r"(addr))

#define LDSM_X4_T(r, addr) \
    asm volatile("ldmatrix.sync.aligned.m8n8.x4.trans.shared.b16 {%0,%1,%2,%3}, [%4];" \
        : "=r"((r)[0]), "=r"((r)[1]), "=r"((r)[2]), "=r"((r)[3]) : "r"(addr))

// bf16 mma (attention path)
#define MMA16816(d, a, b0, b1) \
    asm volatile("mma.sync.aligned.m16n8k16.row.col.f32.bf16.bf16.f32 " \
        "{%0,%1,%2,%3}, {%4,%5,%6,%7}, {%8,%9}, {%0,%1,%2,%3};" \
        : "+f"((d)[0]), "+f"((d)[1]), "+f"((d)[2]), "+f"((d)[3]) \
        : "r"((a)[0]), "r"((a)[1]), "r"((a)[2]), "r"((a)[3]), "r"(b0), "r"(b1))

// fp16 mma (projection GEMMs)
#define MMA16816H(d, a, b0, b1) \
    asm volatile("mma.sync.aligned.m16n8k16.row.col.f32.f16.f16.f32 " \
        "{%0,%1,%2,%3}, {%4,%5,%6,%7}, {%8,%9}, {%0,%1,%2,%3};" \
        : "+f"((d)[0]), "+f"((d)[1]), "+f"((d)[2]), "+f"((d)[3]) \
        : "r"((a)[0]), "r"((a)[1]), "r"((a)[2]), "r"((a)[3]), "r"(b0), "r"(b1))

// Split a pair of floats into packed bf16 hi + bf16 lo (error compensation)
__device__ __forceinline__ void split2(float a, float b, uint32_t& hi, uint32_t& lo) {
    __nv_bfloat16 ah = __float2bfloat16_rn(a);
    __nv_bfloat16 bh = __float2bfloat16_rn(b);
    float ar = a - __bfloat162float(ah);
    float br = b - __bfloat162float(bh);
    __nv_bfloat162 hp; hp.x = ah; hp.y = bh;
    __nv_bfloat162 lp; lp.x = __float2bfloat16_rn(ar); lp.y = __float2bfloat16_rn(br);
    hi = *(uint32_t*)&hp;
    lo = *(uint32_t*)&lp;
}

// Split a pair of floats into packed fp16 hi + fp16 lo (exact to ~2^-22)
__device__ __forceinline__ void split2h(float a, float b, uint32_t& hi, uint32_t& lo) {
    __half ah = __float2half_rn(a);
    __half bh = __float2half_rn(b);
    float ar = a - __half2float(ah);
    float br = b - __half2float(bh);
    __half2 hp; hp.x = ah; hp.y = bh;
    __half2 lp; lp.x = __float2half_rn(ar); lp.y = __float2half_rn(br);
    hi = *(uint32_t*)&hp;
    lo = *(uint32_t*)&lp;
}

// ---------------------------------------------------------------------------
// Merged input prep: x fp16 hi/lo (blocks 0..4095), weights fp16 single
// (blocks 4096..6143), rope table (blocks 6144..6207). One launch.
// ---------------------------------------------------------------------------
__global__ void prep_inputs(const float* __restrict__ x,
                            const float* __restrict__ w0, const float* __restrict__ w1,
                            const float* __restrict__ w2, const float* __restrict__ w3)
{
    const int blk = blockIdx.x;
    const int tid = threadIdx.x;

    if (blk < 4096) {
        // x -> g_xc (fp16 hi/lo split)
        int i = blk * 256 + tid;
        int row = i >> 7;
        int c8 = (i & 127) * 8;
        const float* s = x + (size_t)row * 1024 + c8;
        float4 v0 = *(const float4*)(s);
        float4 v1 = *(const float4*)(s + 4);
        float vs[8] = {v0.x, v0.y, v0.z, v0.w, v1.x, v1.y, v1.z, v1.w};
        uint32_t hw[4], lw[4];
#pragma unroll
        for (int j = 0; j < 4; j++) split2h(vs[2 * j], vs[2 * j + 1], hw[j], lw[j]);
        *(uint4*)(g_xc + (size_t)row * 2048 + c8)        = make_uint4(hw[0], hw[1], hw[2], hw[3]);
        *(uint4*)(g_xc + (size_t)row * 2048 + 1024 + c8) = make_uint4(lw[0], lw[1], lw[2], lw[3]);
    } else if (blk < 6144) {
        // weights -> g_wc (single fp16 plane)
        int wb = blk - 4096;
        int which = wb >> 9;              // 0..3
        int i = (wb & 511) * 256 + tid;
        int row = i >> 7;
        int c8 = (i & 127) * 8;
        const float* src = ((which == 0) ? w0 : (which == 1) ? w1
                         : (which == 2) ? w2 : w3) + (size_t)row * 1024 + c8;
        float4 v0 = *(const float4*)(src);
        float4 v1 = *(const float4*)(src + 4);
        float vs[8] = {v0.x, v0.y, v0.z, v0.w, v1.x, v1.y, v1.z, v1.w};
        uint32_t hw[4];
#pragma unroll
        for (int j = 0; j < 4; j++) {
            __half2 hp;
            hp.x = __float2half_rn(vs[2 * j]);
            hp.y = __float2half_rn(vs[2 * j + 1]);
            hw[j] = *(uint32_t*)&hp;
        }
        *(uint4*)(g_wc[which] + (size_t)row * 1024 + c8) = make_uint4(hw[0], hw[1], hw[2], hw[3]);
    } else {
        // rope table
        int t = (blk - 6144) * 256 + tid;   // 512*32
        int d = t & 31;
        int s = t >> 5;
        float inv = expf(-(float)d * (9.210340371976184f / 32.0f));
        float ang = (float)s * inv;
        float sn, cs;
        sincosf(ang, &sn, &cs);
        g_rope[s][d] = cs;
        g_rope[s][d + 32] = sn;
    }
}

// ---------------------------------------------------------------------------
// bf16 hi/lo plane write for attention operands (x[0..15]=cols c0..,
// x[16..31]=cols c0+32..), dst layout [plane][S][64].
// ---------------------------------------------------------------------------
__device__ __forceinline__ void prep_write(const float* __restrict__ x,
                                           __nv_bfloat16* __restrict__ basehi,
                                           int s, int c0)
{
    uint32_t hi[16], lo[16];
#pragma unroll
    for (int p = 0; p < 8; p++)  split2(x[2 * p], x[2 * p + 1], hi[p], lo[p]);
#pragma unroll
    for (int p = 0; p < 8; p++)  split2(x[16 + 2 * p], x[17 + 2 * p], hi[8 + p], lo[8 + p]);

    __nv_bfloat16* ph = basehi + (size_t)s * 64;
    __nv_bfloat16* pl = basehi + (size_t)S_ * 64 + (size_t)s * 64;
    *(uint4*)(ph + c0)      = make_uint4(hi[0], hi[1], hi[2], hi[3]);
    *(uint4*)(ph + c0 + 8)  = make_uint4(hi[4], hi[5], hi[6], hi[7]);
    *(uint4*)(ph + c0 + 32) = make_uint4(hi[8], hi[9], hi[10], hi[11]);
    *(uint4*)(ph + c0 + 40) = make_uint4(hi[12], hi[13], hi[14], hi[15]);
    *(uint4*)(pl + c0)      = make_uint4(lo[0], lo[1], lo[2], lo[3]);
    *(uint4*)(pl + c0 + 8)  = make_uint4(lo[4], lo[5], lo[6], lo[7]);
    *(uint4*)(pl + c0 + 32) = make_uint4(lo[8], lo[9], lo[10], lo[11]);
    *(uint4*)(pl + c0 + 40) = make_uint4(lo[12], lo[13], lo[14], lo[15]);
}

// ---------------------------------------------------------------------------
// HMMA GEMM (fp16 2-pass): C[m,n] = sum_k A[m,k]*W[n,k].
// A = g_xc fp16 hi|lo (exact split), W = single fp16 plane; K_eff = 2048.
// CTA 128x128 (8 warps, warp tile 64x32), 3-stage cp.async ring, SW128,
// single __syncthreads per chunk, 2 CTAs/SM.
// QKV variant: fused RoPE + bf16 hi/lo split epilogue -> g_qc/g_kc/g_vc.
// OUT variant: Wo, plain fp32 write.
// ---------------------------------------------------------------------------
#define NCHUNK 32                 // 2 segments (A-hi, A-lo) x 16 chunks of K=64
#define TILE_BYTES 16384          // 128 rows x 128 bytes
#define BUF_BYTES  (2 * TILE_BYTES)
#define NSTAGE 3
#define GEMM_SMEM  (NSTAGE * BUF_BYTES)   // 98304

template<bool QKV>
__device__ __forceinline__ void gemm_body(float* __restrict__ out, int zmode)
{
    extern __shared__ char smc[];
    const uint32_t smem_base = smem_u32(smc);
    const int tid  = threadIdx.x;
    const int wid  = tid >> 5;
    const int lane = tid & 31;
    const int wm   = wid >> 2;      // 0..1
    const int wn   = wid & 3;       // 0..3

    const int n0 = blockIdx.x * 128;
    const int m0 = blockIdx.y * 128;

    const __half* __restrict__ Wsrc = g_wc[QKV ? zmode : 3];

    const int r0  = tid >> 3;
    const int c16 = tid & 7;
    const __half* aGm0 = g_xc + (size_t)(m0 + r0) * 2048 + c16 * 8;
    const __half* bGm0 = Wsrc + (size_t)(n0 + r0) * 1024 + c16 * 8;
    const uint32_t aSm0 = SW128((uint32_t)(r0 * 128 + c16 * 16));
    const uint32_t bSm0 = TILE_BYTES + SW128((uint32_t)(r0 * 128 + c16 * 16));

    uint32_t aRow[4];
#pragma unroll
    for (int i = 0; i < 4; i++)
        aRow[i] = (uint32_t)((wm * 64 + i * 16 + (lane & 15)) * 128 + (lane >> 4) * 16);
    uint32_t bRow[2];
#pragma unroll
    for (int g = 0; g < 2; g++)
        bRow[g] = (uint32_t)(TILE_BYTES +
                  (wn * 32 + g * 16 + ((lane >> 4) & 1) * 8 + (lane & 7)) * 128 +
                  ((lane >> 3) & 1) * 16);

    float acc[4][4][4];
#pragma unroll
    for (int i = 0; i < 4; i++)
#pragma unroll
        for (int j = 0; j < 4; j++)
#pragma unroll
            for (int r = 0; r < 4; r++) acc[i][j][r] = 0.f;

    auto issue = [&](int c) {
        const int seg = c >> 4;                 // 0: A-hi, 1: A-lo
        const int kc  = (c & 15) * 64;
        const int ka  = kc + seg * 1024;
        const uint32_t base = smem_base + (uint32_t)(c % NSTAGE) * BUF_BYTES;
#pragma unroll
        for (int i = 0; i < 4; i++)
            cp16(base + aSm0 + i * 4096u, aGm0 + ka + (size_t)i * 32 * 2048);
#pragma unroll
        for (int i = 0; i < 4; i++)
            cp16(base + bSm0 + i * 4096u, bGm0 + kc + (size_t)i * 32 * 1024);
        CP_COMMIT();
    };

    issue(0);
    issue(1);

    for (int c = 0; c < NCHUNK; c++) {
        if (c + 2 < NCHUNK) {
            CP_WAIT(1);
            __syncthreads();      // stage c visible; all warps done with stage c-1
            issue(c + 2);         // overwrites stage (c-1)%3 — safe after sync
        } else {
            CP_WAIT(0);
            __syncthreads();
        }

        const uint32_t base = smem_base + (uint32_t)(c % NSTAGE) * BUF_BYTES;
#pragma unroll
        for (int ks = 0; ks < 4; ks++) {
            const uint32_t kb32 = (uint32_t)(ks * 32);
            uint32_t af[4][4], bf[2][4];
#pragma unroll
            for (int i = 0; i < 4; i++)
                LDSM_X4(af[i], base + SW128(aRow[i] + kb32));
#pragma unroll
            for (int g = 0; g < 2; g++)
                LDSM_X4(bf[g], base + SW128(bRow[g] + kb32));
#pragma unroll
            for (int i = 0; i < 4; i++) {
#pragma unroll
                for (int j = 0; j < 4; j++) {
                    const uint32_t* bb = bf[j >> 1];
                    MMA16816H(acc[i][j], af[i], bb[(j & 1) * 2], bb[(j & 1) * 2 + 1]);
                }
            }
        }
    }

    const int r4 = lane >> 2;
    const int c2 = (lane & 3) * 2;

    if (!QKV) {
        // Plain fp32 epilogue
#pragma unroll
        for (int i = 0; i < 4; i++) {
            const int mbase = m0 + wm * 64 + i * 16 + r4;
#pragma unroll
            for (int j = 0; j < 4; j++) {
                const int n = n0 + wn * 32 + j * 8 + c2;
#pragma unroll
                for (int rr = 0; rr < 2; rr++) {
                    const int m = mbase + rr * 8;
                    float2 val;
                    val.x = acc[i][j][rr * 2 + 0];
                    val.y = acc[i][j][rr * 2 + 1];
                    *(float2*)(out + (size_t)m * D_ + n) = val;
                }
            }
        }
        return;
    }

    // ---- Fused QKV epilogue: stage fp32 tile via ring smem, rope + split ----
    __syncthreads();              // all warps done with last LDSM reads
    float* sf = (float*)smc;      // reuse ring: 128 x 132 fp32 (67.5 KB)
#pragma unroll
    for (int i = 0; i < 4; i++) {
#pragma unroll
        for (int j = 0; j < 4; j++) {
            const int nl = wn * 32 + j * 8 + c2;
#pragma unroll
            for (int rr = 0; rr < 2; rr++) {
                const int ml = wm * 64 + i * 16 + rr * 8 + r4;
                sf[ml * 132 + nl]     = acc[i][j][rr * 2 + 0];
                sf[ml * 132 + nl + 1] = acc[i][j][rr * 2 + 1];
            }
        }
    }
    __syncthreads();

    __nv_bfloat16* dstbase = (zmode == 0) ? g_qc : (zmode == 1) ? g_kc : g_vc;

#pragma unroll
    for (int it = 0; it < 2; it++) {
        const int u    = tid + 256 * it;       // 512 units: 128 rows x 2 heads x 2 halves
        const int r    = u >> 2;
        const int hh   = (u >> 1) & 1;
        const int half = u & 1;
        const int c0   = half * 16;

        const int m = m0 + r;
        const int s = m & 511;
        const int bcur = m >> 9;
        const int hglob = (n0 >> 6) + hh;
        const size_t plane = (size_t)(bcur * H_ + hglob) * 2 * S_ * 64;

        const float* srow = sf + r * 132 + hh * 64;
        float x[32];
#pragma unroll
        for (int j2 = 0; j2 < 4; j2++) {
            *(float4*)&x[j2 * 4]      = *(const float4*)(srow + c0 + j2 * 4);
            *(float4*)&x[16 + j2 * 4] = *(const float4*)(srow + c0 + 32 + j2 * 4);
        }

        if (zmode != 2) {
            const float* tab = g_rope[s];
            const float sc = (zmode == 0) ? 0.125f : 1.0f;
#pragma unroll
            for (int j2 = 0; j2 < 16; j2++) {
                const float csv = tab[c0 + j2] * sc;
                const float snv = tab[c0 + j2 + 32] * sc;
                const float a = x[j2], b2v = x[16 + j2];
                x[j2]      = a * csv - b2v * snv;
                x[16 + j2] = b2v * csv + a * snv;
            }
        }
        prep_write(x, dstbase + plane, s, c0);
    }
}

__global__ void __launch_bounds__(256, 2) gemm_qkv()
{
    gemm_body<true>(nullptr, blockIdx.z);
}

__global__ void __launch_bounds__(256, 2) gemm_out(float* __restrict__ out)
{
    gemm_body<false>(out, 3);
}

// ---------------------------------------------------------------------------
// HMMA causal flash attention (bf16 3-pass, unchanged numerics).
// Block = (qb, h, b); 128 threads = 4 warps; warp w owns 16 query rows.
// Q fragments loaded directly from gmem; 2-stage KV ring (64KB) -> 3 CTAs/SM.
// Epilogue writes fp16 hi/lo to g_xc for the OUT GEMM.
// ---------------------------------------------------------------------------
#define ATT_STB  32768
#define ATT_SMEM (2 * ATT_STB)   // 65536

// cp.async one 64x64 bf16 plane (8KB) into SW128-swizzled smem
__device__ __forceinline__ void cpa_plane(uint32_t dst, const __nv_bfloat16* __restrict__ src,
                                          int tid)
{
#pragma unroll
    for (int i = 0; i < 4; i++) {
        int u = tid + 128 * i;
        int r = u >> 3, ch = u & 7;
        cp16(dst + SW128((uint32_t)(r * 128 + ch * 16)), src + (size_t)r * 64 + ch * 8);
    }
}

__global__ void __launch_bounds__(128, 3) attn_mma()
{
    extern __shared__ char sm[];
    const uint32_t sb = smem_u32(sm);

    const int tid  = threadIdx.x;
    const int lane = tid & 31;
    const int w    = tid >> 5;
    const int qb = blockIdx.x;
    const int h  = blockIdx.y;
    const int b  = blockIdx.z;
    const int q0 = qb * 64;
    const int bh = b * H_ + h;

    const size_t plane = (size_t)bh * 2 * S_ * 64;
    const size_t LO = (size_t)S_ * 64;
    const __nv_bfloat16* Qc = g_qc + plane;
    const __nv_bfloat16* Kc = g_kc + plane;
    const __nv_bfloat16* Vc = g_vc + plane;

    const int i7  = lane & 7;
    const int grp = lane >> 3;

    auto issue_kv = [&](int kb) {
        const uint32_t st = sb + (uint32_t)(kb & 1) * ATT_STB;
        const int k0 = kb * 64;
        cpa_plane(st,         Kc + (size_t)k0 * 64,      tid);
        cpa_plane(st + 8192,  Kc + LO + (size_t)k0 * 64, tid);
        cpa_plane(st + 16384, Vc + (size_t)k0 * 64,      tid);
        cpa_plane(st + 24576, Vc + LO + (size_t)k0 * 64, tid);
        CP_COMMIT();
    };

    issue_kv(0);
    if (qb >= 1) issue_kv(1);

    // ---- Q fragments straight from gmem (bit-identical to ldmatrix path) ----
    uint32_t qh[4][4], ql[4][4];
    {
        const int rowA = q0 + w * 16 + (lane >> 2);
        const int rowB = rowA + 8;
        const int cc = (lane & 3) * 2;
#pragma unroll
        for (int kc = 0; kc < 4; kc++) {
            const int col = kc * 16 + cc;
            qh[kc][0] = *(const uint32_t*)&Qc[(size_t)rowA * 64 + col];
            qh[kc][1] = *(const uint32_t*)&Qc[(size_t)rowB * 64 + col];
            qh[kc][2] = *(const uint32_t*)&Qc[(size_t)rowA * 64 + col + 8];
            qh[kc][3] = *(const uint32_t*)&Qc[(size_t)rowB * 64 + col + 8];
            ql[kc][0] = *(const uint32_t*)&Qc[LO + (size_t)rowA * 64 + col];
            ql[kc][1] = *(const uint32_t*)&Qc[LO + (size_t)rowB * 64 + col];
            ql[kc][2] = *(const uint32_t*)&Qc[LO + (size_t)rowA * 64 + col + 8];
            ql[kc][3] = *(const uint32_t*)&Qc[LO + (size_t)rowB * 64 + col + 8];
        }
    }

    float mr0 = -1e30f, mr1 = -1e30f;
    float l0 = 0.f, l1 = 0.f;
    float O[8][4];
#pragma unroll
    for (int i = 0; i < 8; i++)
#pragma unroll
        for (int j = 0; j < 4; j++) O[i][j] = 0.f;

    for (int kb = 0; kb <= qb; kb++) {
        if (kb + 1 <= qb) { CP_WAIT(1); } else { CP_WAIT(0); }
        __syncthreads();          // stage kb ready for all warps

        const uint32_t st = sb + (uint32_t)(kb & 1) * ATT_STB;
        const uint32_t KH = st, KL = st + 8192, VH = st + 16384, VL = st + 24576;

        // ---- Scores S[64q x 64k] per warp, 3 error-comp passes ----
        float S[8][4];
#pragma unroll
        for (int i = 0; i < 8; i++)
#pragma unroll
            for (int j = 0; j < 4; j++) S[i][j] = 0.f;

#pragma unroll
        for (int kc = 0; kc < 4; kc++) {
#pragma unroll
            for (int n2 = 0; n2 < 4; n2++) {
                const int row = n2 * 16 + (grp >> 1) * 8 + i7;
                const uint32_t kbyte = (uint32_t)(kc * 32 + (grp & 1) * 16);
                uint32_t bhf[4], blf[4];
                LDSM_X4(bhf, KH + SW128((uint32_t)(row * 128) + kbyte));
                LDSM_X4(blf, KL + SW128((uint32_t)(row * 128) + kbyte));
                MMA16816(S[n2 * 2],     qh[kc], bhf[0], bhf[1]);
                MMA16816(S[n2 * 2 + 1], qh[kc], bhf[2], bhf[3]);
                MMA16816(S[n2 * 2],     ql[kc], bhf[0], bhf[1]);
                MMA16816(S[n2 * 2 + 1], ql[kc], bhf[2], bhf[3]);
                MMA16816(S[n2 * 2],     qh[kc], blf[0], blf[1]);
                MMA16816(S[n2 * 2 + 1], qh[kc], blf[2], blf[3]);
            }
        }

        // ---- Causal mask (diagonal block only) ----
        if (kb == qb) {
            const int rloc0 = w * 16 + (lane >> 2);
            const int cbase = (lane & 3) * 2;
#pragma unroll
            for (int jt = 0; jt < 8; jt++) {
                const int c = jt * 8 + cbase;
                if (c     > rloc0)     S[jt][0] = -1e30f;
                if (c + 1 > rloc0)     S[jt][1] = -1e30f;
                if (c     > rloc0 + 8) S[jt][2] = -1e30f;
                if (c + 1 > rloc0 + 8) S[jt][3] = -1e30f;
            }
        }

        // ---- Online softmax ----
        float bm0 = -1e30f, bm1 = -1e30f;
#pragma unroll
        for (int jt = 0; jt < 8; jt++) {
            bm0 = fmaxf(bm0, fmaxf(S[jt][0], S[jt][1]));
            bm1 = fmaxf(bm1, fmaxf(S[jt][2], S[jt][3]));
        }
        bm0 = fmaxf(bm0, __shfl_xor_sync(0xFFFFFFFF, bm0, 1));
        bm0 = fmaxf(bm0, __shfl_xor_sync(0xFFFFFFFF, bm0, 2));
        bm1 = fmaxf(bm1, __shfl_xor_sync(0xFFFFFFFF, bm1, 1));
        bm1 = fmaxf(bm1, __shfl_xor_sync(0xFFFFFFFF, bm1, 2));

        const float mn0 = fmaxf(mr0, bm0);
        const float mn1 = fmaxf(mr1, bm1);
        const float corr0 = exp2f((mr0 - mn0) * LOG2E);
        const float corr1 = exp2f((mr1 - mn1) * LOG2E);
        mr0 = mn0; mr1 = mn1;
        l0 *= corr0; l1 *= corr1;

        float P[8][4];
#pragma unroll
        for (int jt = 0; jt < 8; jt++) {
            P[jt][0] = exp2f((S[jt][0] - mn0) * LOG2E);
            P[jt][1] = exp2f((S[jt][1] - mn0) * LOG2E);
            P[jt][2] = exp2f((S[jt][2] - mn1) * LOG2E);
            P[jt][3] = exp2f((S[jt][3] - mn1) * LOG2E);
            l0 += P[jt][0] + P[jt][1];
            l1 += P[jt][2] + P[jt][3];
        }
#pragma unroll
        for (int dt = 0; dt < 8; dt++) {
            O[dt][0] *= corr0; O[dt][1] *= corr0;
            O[dt][2] *= corr1; O[dt][3] *= corr1;
        }

        // ---- P A-fragments (hi/lo) from C-fragment layout ----
        uint32_t ph[4][4], pl[4][4];
#pragma unroll
        for (int kc = 0; kc < 4; kc++) {
            split2(P[2 * kc][0],     P[2 * kc][1],     ph[kc][0], pl[kc][0]);
            split2(P[2 * kc][2],     P[2 * kc][3],     ph[kc][1], pl[kc][1]);
            split2(P[2 * kc + 1][0], P[2 * kc + 1][1], ph[kc][2], pl[kc][2]);
            split2(P[2 * kc + 1][2], P[2 * kc + 1][3], ph[kc][3], pl[kc][3]);
        }

        // ---- PV, 3 error-comp passes (V via ldmatrix.trans) ----
#pragma unroll
        for (int kc = 0; kc < 4; kc++) {
#pragma unroll
            for (int d2 = 0; d2 < 4; d2++) {
                const int row = kc * 16 + (grp & 1) * 8 + i7;
                const uint32_t dbyte = (uint32_t)(d2 * 32 + (grp >> 1) * 16);
                uint32_t bhf[4], blf[4];
                LDSM_X4_T(bhf, VH + SW128((uint32_t)(row * 128) + dbyte));
                LDSM_X4_T(blf, VL + SW128((uint32_t)(row * 128) + dbyte));
                MMA16816(O[d2 * 2],     ph[kc], bhf[0], bhf[1]);
                MMA16816(O[d2 * 2 + 1], ph[kc], bhf[2], bhf[3]);
                MMA16816(O[d2 * 2],     pl[kc], bhf[0], bhf[1]);
                MMA16816(O[d2 * 2 + 1], pl[kc], bhf[2], bhf[3]);
                MMA16816(O[d2 * 2],     ph[kc], blf[0], blf[1]);
                MMA16816(O[d2 * 2 + 1], ph[kc], blf[2], blf[3]);
            }
        }

        // Re-issue into the buffer we just finished reading (2-stage ring).
        if (kb + 2 <= qb) {
            __syncthreads();      // all warps done reading stage kb
            issue_kv(kb + 2);
        }
    }

    // ---- Final l reduction + normalized fp16 hi/lo write to g_xc ----
    l0 += __shfl_xor_sync(0xFFFFFFFF, l0, 1);
    l0 += __shfl_xor_sync(0xFFFFFFFF, l0, 2);
    l1 += __shfl_xor_sync(0xFFFFFFFF, l1, 1);
    l1 += __shfl_xor_sync(0xFFFFFFFF, l1, 2);
    const float inv0 = 1.0f / l0;
    const float inv1 = 1.0f / l1;

    const int rA = q0 + w * 16 + (lane >> 2);
    const int rB = rA + 8;
    const size_t tA = ((size_t)(b * S_ + rA)) * 2048;
    const size_t tB = ((size_t)(b * S_ + rB)) * 2048;
    const int colbase = h * 64 + (lane & 3) * 2;

#pragma unroll
    for (int dt = 0; dt < 8; dt++) {
        const int col = colbase + dt * 8;
        uint32_t hi, lo;
        split2h(O[dt][0] * inv0, O[dt][1] * inv0, hi, lo);
        *(uint32_t*)&g_xc[tA + col]        = hi;
        *(uint32_t*)&g_xc[tA + 1024 + col] = lo;
        split2h(O[dt][2] * inv1, O[dt][3] * inv1, hi, lo);
        *(uint32_t*)&g_xc[tB + col]        = hi;
        *(uint32_t*)&g_xc[tB + 1024 + col] = lo;
    }
}

// ---------------------------------------------------------------------------
extern "C" void kernel_launch(void* const* d_in, const int* in_sizes, int n_in,
                              void* d_out, int out_size)
{
    const float* x  = (const float*)d_in[0];
    const float* Wq = (const float*)d_in[1];
    const float* Wk = (const float*)d_in[2];
    const float* Wv = (const float*)d_in[3];
    const float* Wo = (const float*)d_in[4];
    float* out = (float*)d_out;

    cudaFuncSetAttribute(gemm_qkv, cudaFuncAttributeMaxDynamicSharedMemorySize, GEMM_SMEM);
    cudaFuncSetAttribute(gemm_out, cudaFuncAttributeMaxDynamicSharedMemorySize, GEMM_SMEM);
    cudaFuncSetAttribute(attn_mma, cudaFuncAttributeMaxDynamicSharedMemorySize, ATT_SMEM);

    // One merged prep launch: x fp16-split | weight fp16 | rope table
    prep_inputs<<<6208, 256>>>(x, Wq, Wk, Wv, Wo);

    // Merged QKV projections (fp16 2-pass) with fused RoPE + bf16 split epilogue
    gemm_qkv<<<dim3(D_ / 128, TOK / 128, 3), 256, GEMM_SMEM>>>();

    attn_mma<<<dim3(S_ / 64, H_, B_), 128, ATT_SMEM>>>();

    gemm_out<<<dim3(D_ / 128, TOK / 128), 256, GEMM_SMEM>>>(out);
}

// round 16
// speedup vs baseline: 2.1387x; 1.5221x over previous
#include <cuda_runtime.h>
#include <cuda_bf16.h>
#include <cuda_fp16.h>
#include <math.h>
#include <stdint.h>

// Problem constants
#define B_  16
#define S_  512
#define D_  1024
#define H_  16
#define HD_ 64
#define TOK (B_ * S_)            // 8192 tokens

// Scratch (device globals; no dynamic allocation allowed)
__device__ float g_rope[S_][64];              // [s][0:32)=cos, [32:64)=sin

// fp16 activations (single plane): [TOK, 1024]
__device__ __half g_xc[(size_t)TOK * 1024];
// weights: single fp16 plane, 4 x [1024, 1024]
__device__ __half g_wc[4][(size_t)D_ * 1024];
// prepped attention operands (bf16, 3-pass path): [bh][plane(hi/lo)][S][64]
__device__ __nv_bfloat16 g_qc[(size_t)B_ * H_ * 2 * S_ * 64];
__device__ __nv_bfloat16 g_kc[(size_t)B_ * H_ * 2 * S_ * 64];
__device__ __nv_bfloat16 g_vc[(size_t)B_ * H_ * 2 * S_ * 64];

#define LOG2E 1.4426950408889634f

// ---------------------------------------------------------------------------
// Helpers (family-portable PTX only: ldmatrix / mma.sync / cp.async)
// ---------------------------------------------------------------------------
__device__ __forceinline__ uint32_t smem_u32(const void* p) {
    uint32_t a;
    asm("{ .reg .u64 t; cvta.to.shared.u64 t, %1; cvt.u32.u64 %0, t; }"
        : "=r"(a) : "l"(p));
    return a;
}

#define SW128(off) ((off) ^ (((off) >> 3) & 0x70))

__device__ __forceinline__ void cp16(uint32_t s, const void* g) {
    asm volatile("cp.async.cg.shared.global [%0], [%1], 16;" :: "r"(s), "l"(g));
}
#define CP_COMMIT() asm volatile("cp.async.commit_group;" ::: "memory")
#define CP_WAIT(n)  asm volatile("cp.async.wait_group %0;" :: "n"(n) : "memory")

#define LDSM_X4(r, addr) \
    asm volatile("ldmatrix.sync.aligned.m8n8.x4.shared.b16 {%0,%1,%2,%3}, [%4];" \
        : "=r"((r)[0]), "=r"((r)[1]), "=r"((r)[2]), "=r"((r)[3]) : "r"(addr))

#define LDSM_X4_T(r, addr) \
    asm volatile("ldmatrix.sync.aligned.m8n8.x4.trans.shared.b16 {%0,%1,%2,%3}, [%4];" \
        : "=r"((r)[0]), "=r"((r)[1]), "=r"((r)[2]), "=r"((r)[3]) : "r"(addr))

// bf16 mma (attention path)
#define MMA16816(d, a, b0, b1) \
    asm volatile("mma.sync.aligned.m16n8k16.row.col.f32.bf16.bf16.f32 " \
        "{%0,%1,%2,%3}, {%4,%5,%6,%7}, {%8,%9}, {%0,%1,%2,%3};" \
        : "+f"((d)[0]), "+f"((d)[1]), "+f"((d)[2]), "+f"((d)[3]) \
        : "r"((a)[0]), "r"((a)[1]), "r"((a)[2]), "r"((a)[3]), "r"(b0), "r"(b1))

// fp16 mma (projection GEMMs)
#define MMA16816H(d, a, b0, b1) \
    asm volatile("mma.sync.aligned.m16n8k16.row.col.f32.f16.f16.f32 " \
        "{%0,%1,%2,%3}, {%4,%5,%6,%7}, {%8,%9}, {%0,%1,%2,%3};" \
        : "+f"((d)[0]), "+f"((d)[1]), "+f"((d)[2]), "+f"((d)[3]) \
        : "r"((a)[0]), "r"((a)[1]), "r"((a)[2]), "r"((a)[3]), "r"(b0), "r"(b1))

// Split a pair of floats into packed bf16 hi + bf16 lo (error compensation)
__device__ __forceinline__ void split2(float a, float b, uint32_t& hi, uint32_t& lo) {
    __nv_bfloat16 ah = __float2bfloat16_rn(a);
    __nv_bfloat16 bh = __float2bfloat16_rn(b);
    float ar = a - __bfloat162float(ah);
    float br = b - __bfloat162float(bh);
    __nv_bfloat162 hp; hp.x = ah; hp.y = bh;
    __nv_bfloat162 lp; lp.x = __float2bfloat16_rn(ar); lp.y = __float2bfloat16_rn(br);
    hi = *(uint32_t*)&hp;
    lo = *(uint32_t*)&lp;
}

// Pack a pair of floats into fp16x2 (round-to-nearest)
__device__ __forceinline__ uint32_t pack2h(float a, float b) {
    __half2 hp;
    hp.x = __float2half_rn(a);
    hp.y = __float2half_rn(b);
    return *(uint32_t*)&hp;
}

// ---------------------------------------------------------------------------
// Merged input prep: x fp16 (blocks 0..4095), weights fp16 (blocks
// 4096..6143), rope table (blocks 6144..6207). One launch.
// ---------------------------------------------------------------------------
__global__ void prep_inputs(const float* __restrict__ x,
                            const float* __restrict__ w0, const float* __restrict__ w1,
                            const float* __restrict__ w2, const float* __restrict__ w3)
{
    const int blk = blockIdx.x;
    const int tid = threadIdx.x;

    if (blk < 6144) {
        const float* src;
        __half* dst;
        if (blk < 4096) {
            int i = blk * 256 + tid;
            int row = i >> 7;
            int c8 = (i & 127) * 8;
            src = x + (size_t)row * 1024 + c8;
            dst = g_xc + (size_t)row * 1024 + c8;
        } else {
            int wb = blk - 4096;
            int which = wb >> 9;              // 0..3
            int i = (wb & 511) * 256 + tid;
            int row = i >> 7;
            int c8 = (i & 127) * 8;
            src = ((which == 0) ? w0 : (which == 1) ? w1
                 : (which == 2) ? w2 : w3) + (size_t)row * 1024 + c8;
            dst = g_wc[which] + (size_t)row * 1024 + c8;
        }
        float4 v0 = *(const float4*)(src);
        float4 v1 = *(const float4*)(src + 4);
        uint4 o;
        o.x = pack2h(v0.x, v0.y);
        o.y = pack2h(v0.z, v0.w);
        o.z = pack2h(v1.x, v1.y);
        o.w = pack2h(v1.z, v1.w);
        *(uint4*)dst = o;
    } else {
        // rope table
        int t = (blk - 6144) * 256 + tid;   // 512*32
        int d = t & 31;
        int s = t >> 5;
        float inv = expf(-(float)d * (9.210340371976184f / 32.0f));
        float ang = (float)s * inv;
        float sn, cs;
        sincosf(ang, &sn, &cs);
        g_rope[s][d] = cs;
        g_rope[s][d + 32] = sn;
    }
}

// ---------------------------------------------------------------------------
// bf16 hi/lo plane write for attention operands (x[0..15]=cols c0..,
// x[16..31]=cols c0+32..), dst layout [plane][S][64].
// ---------------------------------------------------------------------------
__device__ __forceinline__ void prep_write(const float* __restrict__ x,
                                           __nv_bfloat16* __restrict__ basehi,
                                           int s, int c0)
{
    uint32_t hi[16], lo[16];
#pragma unroll
    for (int p = 0; p < 8; p++)  split2(x[2 * p], x[2 * p + 1], hi[p], lo[p]);
#pragma unroll
    for (int p = 0; p < 8; p++)  split2(x[16 + 2 * p], x[17 + 2 * p], hi[8 + p], lo[8 + p]);

    __nv_bfloat16* ph = basehi + (size_t)s * 64;
    __nv_bfloat16* pl = basehi + (size_t)S_ * 64 + (size_t)s * 64;
    *(uint4*)(ph + c0)      = make_uint4(hi[0], hi[1], hi[2], hi[3]);
    *(uint4*)(ph + c0 + 8)  = make_uint4(hi[4], hi[5], hi[6], hi[7]);
    *(uint4*)(ph + c0 + 32) = make_uint4(hi[8], hi[9], hi[10], hi[11]);
    *(uint4*)(ph + c0 + 40) = make_uint4(hi[12], hi[13], hi[14], hi[15]);
    *(uint4*)(pl + c0)      = make_uint4(lo[0], lo[1], lo[2], lo[3]);
    *(uint4*)(pl + c0 + 8)  = make_uint4(lo[4], lo[5], lo[6], lo[7]);
    *(uint4*)(pl + c0 + 32) = make_uint4(lo[8], lo[9], lo[10], lo[11]);
    *(uint4*)(pl + c0 + 40) = make_uint4(lo[12], lo[13], lo[14], lo[15]);
}

// ---------------------------------------------------------------------------
// HMMA GEMM (fp16 single-pass): C[m,n] = sum_k A[m,k]*W[n,k], K = 1024.
// CTA 128x128 (8 warps, warp tile 64x32), 3-stage cp.async ring, SW128,
// single __syncthreads per chunk, 2 CTAs/SM.
// QKV variant: fused RoPE + bf16 hi/lo split epilogue -> g_qc/g_kc/g_vc.
// OUT variant: Wo, plain fp32 write.
// ---------------------------------------------------------------------------
#define NCHUNK 16                 // 16 chunks of K=64 fp16
#define TILE_BYTES 16384          // 128 rows x 128 bytes
#define BUF_BYTES  (2 * TILE_BYTES)
#define NSTAGE 3
#define GEMM_SMEM  (NSTAGE * BUF_BYTES)   // 98304

template<bool QKV>
__device__ __forceinline__ void gemm_body(float* __restrict__ out, int zmode)
{
    extern __shared__ char smc[];
    const uint32_t smem_base = smem_u32(smc);
    const int tid  = threadIdx.x;
    const int wid  = tid >> 5;
    const int lane = tid & 31;
    const int wm   = wid >> 2;      // 0..1
    const int wn   = wid & 3;       // 0..3

    const int n0 = blockIdx.x * 128;
    const int m0 = blockIdx.y * 128;

    const __half* __restrict__ Wsrc = g_wc[QKV ? zmode : 3];

    const int r0  = tid >> 3;
    const int c16 = tid & 7;
    const __half* aGm0 = g_xc + (size_t)(m0 + r0) * 1024 + c16 * 8;
    const __half* bGm0 = Wsrc + (size_t)(n0 + r0) * 1024 + c16 * 8;
    const uint32_t aSm0 = SW128((uint32_t)(r0 * 128 + c16 * 16));
    const uint32_t bSm0 = TILE_BYTES + SW128((uint32_t)(r0 * 128 + c16 * 16));

    uint32_t aRow[4];
#pragma unroll
    for (int i = 0; i < 4; i++)
        aRow[i] = (uint32_t)((wm * 64 + i * 16 + (lane & 15)) * 128 + (lane >> 4) * 16);
    uint32_t bRow[2];
#pragma unroll
    for (int g = 0; g < 2; g++)
        bRow[g] = (uint32_t)(TILE_BYTES +
                  (wn * 32 + g * 16 + ((lane >> 4) & 1) * 8 + (lane & 7)) * 128 +
                  ((lane >> 3) & 1) * 16);

    float acc[4][4][4];
#pragma unroll
    for (int i = 0; i < 4; i++)
#pragma unroll
        for (int j = 0; j < 4; j++)
#pragma unroll
            for (int r = 0; r < 4; r++) acc[i][j][r] = 0.f;

    auto issue = [&](int c) {
        const int kc = c * 64;
        const uint32_t base = smem_base + (uint32_t)(c % NSTAGE) * BUF_BYTES;
#pragma unroll
        for (int i = 0; i < 4; i++)
            cp16(base + aSm0 + i * 4096u, aGm0 + kc + (size_t)i * 32 * 1024);
#pragma unroll
        for (int i = 0; i < 4; i++)
            cp16(base + bSm0 + i * 4096u, bGm0 + kc + (size_t)i * 32 * 1024);
        CP_COMMIT();
    };

    issue(0);
    issue(1);

    for (int c = 0; c < NCHUNK; c++) {
        if (c + 2 < NCHUNK) {
            CP_WAIT(1);
            __syncthreads();      // stage c visible; all warps done with stage c-1
            issue(c + 2);         // overwrites stage (c-1)%3 — safe after sync
        } else {
            CP_WAIT(0);
            __syncthreads();
        }

        const uint32_t base = smem_base + (uint32_t)(c % NSTAGE) * BUF_BYTES;
#pragma unroll
        for (int ks = 0; ks < 4; ks++) {
            const uint32_t kb32 = (uint32_t)(ks * 32);
            uint32_t af[4][4], bf[2][4];
#pragma unroll
            for (int i = 0; i < 4; i++)
                LDSM_X4(af[i], base + SW128(aRow[i] + kb32));
#pragma unroll
            for (int g = 0; g < 2; g++)
                LDSM_X4(bf[g], base + SW128(bRow[g] + kb32));
#pragma unroll
            for (int i = 0; i < 4; i++) {
#pragma unroll
                for (int j = 0; j < 4; j++) {
                    const uint32_t* bb = bf[j >> 1];
                    MMA16816H(acc[i][j], af[i], bb[(j & 1) * 2], bb[(j & 1) * 2 + 1]);
                }
            }
        }
    }

    const int r4 = lane >> 2;
    const int c2 = (lane & 3) * 2;

    if (!QKV) {
        // Plain fp32 epilogue
#pragma unroll
        for (int i = 0; i < 4; i++) {
            const int mbase = m0 + wm * 64 + i * 16 + r4;
#pragma unroll
            for (int j = 0; j < 4; j++) {
                const int n = n0 + wn * 32 + j * 8 + c2;
#pragma unroll
                for (int rr = 0; rr < 2; rr++) {
                    const int m = mbase + rr * 8;
                    float2 val;
                    val.x = acc[i][j][rr * 2 + 0];
                    val.y = acc[i][j][rr * 2 + 1];
                    *(float2*)(out + (size_t)m * D_ + n) = val;
                }
            }
        }
        return;
    }

    // ---- Fused QKV epilogue: stage fp32 tile via ring smem, rope + split ----
    __syncthreads();              // all warps done with last LDSM reads
    float* sf = (float*)smc;      // reuse ring: 128 x 132 fp32 (67.5 KB)
#pragma unroll
    for (int i = 0; i < 4; i++) {
#pragma unroll
        for (int j = 0; j < 4; j++) {
            const int nl = wn * 32 + j * 8 + c2;
#pragma unroll
            for (int rr = 0; rr < 2; rr++) {
                const int ml = wm * 64 + i * 16 + rr * 8 + r4;
                sf[ml * 132 + nl]     = acc[i][j][rr * 2 + 0];
                sf[ml * 132 + nl + 1] = acc[i][j][rr * 2 + 1];
            }
        }
    }
    __syncthreads();

    __nv_bfloat16* dstbase = (zmode == 0) ? g_qc : (zmode == 1) ? g_kc : g_vc;

#pragma unroll
    for (int it = 0; it < 2; it++) {
        const int u    = tid + 256 * it;       // 512 units: 128 rows x 2 heads x 2 halves
        const int r    = u >> 2;
        const int hh   = (u >> 1) & 1;
        const int half = u & 1;
        const int c0   = half * 16;

        const int m = m0 + r;
        const int s = m & 511;
        const int bcur = m >> 9;
        const int hglob = (n0 >> 6) + hh;
        const size_t plane = (size_t)(bcur * H_ + hglob) * 2 * S_ * 64;

        const float* srow = sf + r * 132 + hh * 64;
        float x[32];
#pragma unroll
        for (int j2 = 0; j2 < 4; j2++) {
            *(float4*)&x[j2 * 4]      = *(const float4*)(srow + c0 + j2 * 4);
            *(float4*)&x[16 + j2 * 4] = *(const float4*)(srow + c0 + 32 + j2 * 4);
        }

        if (zmode != 2) {
            const float* tab = g_rope[s];
            const float sc = (zmode == 0) ? 0.125f : 1.0f;
#pragma unroll
            for (int j2 = 0; j2 < 16; j2++) {
                const float csv = tab[c0 + j2] * sc;
                const float snv = tab[c0 + j2 + 32] * sc;
                const float a = x[j2], b2v = x[16 + j2];
                x[j2]      = a * csv - b2v * snv;
                x[16 + j2] = b2v * csv + a * snv;
            }
        }
        prep_write(x, dstbase + plane, s, c0);
    }
}

__global__ void __launch_bounds__(256, 2) gemm_qkv()
{
    gemm_body<true>(nullptr, blockIdx.z);
}

__global__ void __launch_bounds__(256, 2) gemm_out(float* __restrict__ out)
{
    gemm_body<false>(out, 3);
}

// ---------------------------------------------------------------------------
// HMMA causal flash attention (bf16 3-pass, unchanged numerics).
// Block = (qb, h, b); 128 threads = 4 warps; warp w owns 16 query rows.
// Q fragments loaded directly from gmem; 2-stage KV ring (64KB) -> 3 CTAs/SM.
// Epilogue writes fp16 (single plane) to g_xc for the OUT GEMM.
// ---------------------------------------------------------------------------
#define ATT_STB  32768
#define ATT_SMEM (2 * ATT_STB)   // 65536

// cp.async one 64x64 bf16 plane (8KB) into SW128-swizzled smem
__device__ __forceinline__ void cpa_plane(uint32_t dst, const __nv_bfloat16* __restrict__ src,
                                          int tid)
{
#pragma unroll
    for (int i = 0; i < 4; i++) {
        int u = tid + 128 * i;
        int r = u >> 3, ch = u & 7;
        cp16(dst + SW128((uint32_t)(r * 128 + ch * 16)), src + (size_t)r * 64 + ch * 8);
    }
}

__global__ void __launch_bounds__(128, 3) attn_mma()
{
    extern __shared__ char sm[];
    const uint32_t sb = smem_u32(sm);

    const int tid  = threadIdx.x;
    const int lane = tid & 31;
    const int w    = tid >> 5;
    const int qb = blockIdx.x;
    const int h  = blockIdx.y;
    const int b  = blockIdx.z;
    const int q0 = qb * 64;
    const int bh = b * H_ + h;

    const size_t plane = (size_t)bh * 2 * S_ * 64;
    const size_t LO = (size_t)S_ * 64;
    const __nv_bfloat16* Qc = g_qc + plane;
    const __nv_bfloat16* Kc = g_kc + plane;
    const __nv_bfloat16* Vc = g_vc + plane;

    const int i7  = lane & 7;
    const int grp = lane >> 3;

    auto issue_kv = [&](int kb) {
        const uint32_t st = sb + (uint32_t)(kb & 1) * ATT_STB;
        const int k0 = kb * 64;
        cpa_plane(st,         Kc + (size_t)k0 * 64,      tid);
        cpa_plane(st + 8192,  Kc + LO + (size_t)k0 * 64, tid);
        cpa_plane(st + 16384, Vc + (size_t)k0 * 64,      tid);
        cpa_plane(st + 24576, Vc + LO + (size_t)k0 * 64, tid);
        CP_COMMIT();
    };

    issue_kv(0);
    if (qb >= 1) issue_kv(1);

    // ---- Q fragments straight from gmem (bit-identical to ldmatrix path) ----
    uint32_t qh[4][4], ql[4][4];
    {
        const int rowA = q0 + w * 16 + (lane >> 2);
        const int rowB = rowA + 8;
        const int cc = (lane & 3) * 2;
#pragma unroll
        for (int kc = 0; kc < 4; kc++) {
            const int col = kc * 16 + cc;
            qh[kc][0] = *(const uint32_t*)&Qc[(size_t)rowA * 64 + col];
            qh[kc][1] = *(const uint32_t*)&Qc[(size_t)rowB * 64 + col];
            qh[kc][2] = *(const uint32_t*)&Qc[(size_t)rowA * 64 + col + 8];
            qh[kc][3] = *(const uint32_t*)&Qc[(size_t)rowB * 64 + col + 8];
            ql[kc][0] = *(const uint32_t*)&Qc[LO + (size_t)rowA * 64 + col];
            ql[kc][1] = *(const uint32_t*)&Qc[LO + (size_t)rowB * 64 + col];
            ql[kc][2] = *(const uint32_t*)&Qc[LO + (size_t)rowA * 64 + col + 8];
            ql[kc][3] = *(const uint32_t*)&Qc[LO + (size_t)rowB * 64 + col + 8];
        }
    }

    float mr0 = -1e30f, mr1 = -1e30f;
    float l0 = 0.f, l1 = 0.f;
    float O[8][4];
#pragma unroll
    for (int i = 0; i < 8; i++)
#pragma unroll
        for (int j = 0; j < 4; j++) O[i][j] = 0.f;

    for (int kb = 0; kb <= qb; kb++) {
        if (kb + 1 <= qb) { CP_WAIT(1); } else { CP_WAIT(0); }
        __syncthreads();          // stage kb ready for all warps

        const uint32_t st = sb + (uint32_t)(kb & 1) * ATT_STB;
        const uint32_t KH = st, KL = st + 8192, VH = st + 16384, VL = st + 24576;

        // ---- Scores S[64q x 64k] per warp, 3 error-comp passes ----
        float S[8][4];
#pragma unroll
        for (int i = 0; i < 8; i++)
#pragma unroll
            for (int j = 0; j < 4; j++) S[i][j] = 0.f;

#pragma unroll
        for (int kc = 0; kc < 4; kc++) {
#pragma unroll
            for (int n2 = 0; n2 < 4; n2++) {
                const int row = n2 * 16 + (grp >> 1) * 8 + i7;
                const uint32_t kbyte = (uint32_t)(kc * 32 + (grp & 1) * 16);
                uint32_t bhf[4], blf[4];
                LDSM_X4(bhf, KH + SW128((uint32_t)(row * 128) + kbyte));
                LDSM_X4(blf, KL + SW128((uint32_t)(row * 128) + kbyte));
                MMA16816(S[n2 * 2],     qh[kc], bhf[0], bhf[1]);
                MMA16816(S[n2 * 2 + 1], qh[kc], bhf[2], bhf[3]);
                MMA16816(S[n2 * 2],     ql[kc], bhf[0], bhf[1]);
                MMA16816(S[n2 * 2 + 1], ql[kc], bhf[2], bhf[3]);
                MMA16816(S[n2 * 2],     qh[kc], blf[0], blf[1]);
                MMA16816(S[n2 * 2 + 1], qh[kc], blf[2], blf[3]);
            }
        }

        // ---- Causal mask (diagonal block only) ----
        if (kb == qb) {
            const int rloc0 = w * 16 + (lane >> 2);
            const int cbase = (lane & 3) * 2;
#pragma unroll
            for (int jt = 0; jt < 8; jt++) {
                const int c = jt * 8 + cbase;
                if (c     > rloc0)     S[jt][0] = -1e30f;
                if (c + 1 > rloc0)     S[jt][1] = -1e30f;
                if (c     > rloc0 + 8) S[jt][2] = -1e30f;
                if (c + 1 > rloc0 + 8) S[jt][3] = -1e30f;
            }
        }

        // ---- Online softmax ----
        float bm0 = -1e30f, bm1 = -1e30f;
#pragma unroll
        for (int jt = 0; jt < 8; jt++) {
            bm0 = fmaxf(bm0, fmaxf(S[jt][0], S[jt][1]));
            bm1 = fmaxf(bm1, fmaxf(S[jt][2], S[jt][3]));
        }
        bm0 = fmaxf(bm0, __shfl_xor_sync(0xFFFFFFFF, bm0, 1));
        bm0 = fmaxf(bm0, __shfl_xor_sync(0xFFFFFFFF, bm0, 2));
        bm1 = fmaxf(bm1, __shfl_xor_sync(0xFFFFFFFF, bm1, 1));
        bm1 = fmaxf(bm1, __shfl_xor_sync(0xFFFFFFFF, bm1, 2));

        const float mn0 = fmaxf(mr0, bm0);
        const float mn1 = fmaxf(mr1, bm1);
        const float corr0 = exp2f((mr0 - mn0) * LOG2E);
        const float corr1 = exp2f((mr1 - mn1) * LOG2E);
        mr0 = mn0; mr1 = mn1;
        l0 *= corr0; l1 *= corr1;

        float P[8][4];
#pragma unroll
        for (int jt = 0; jt < 8; jt++) {
            P[jt][0] = exp2f((S[jt][0] - mn0) * LOG2E);
            P[jt][1] = exp2f((S[jt][1] - mn0) * LOG2E);
            P[jt][2] = exp2f((S[jt][2] - mn1) * LOG2E);
            P[jt][3] = exp2f((S[jt][3] - mn1) * LOG2E);
            l0 += P[jt][0] + P[jt][1];
            l1 += P[jt][2] + P[jt][3];
        }
#pragma unroll
        for (int dt = 0; dt < 8; dt++) {
            O[dt][0] *= corr0; O[dt][1] *= corr0;
            O[dt][2] *= corr1; O[dt][3] *= corr1;
        }

        // ---- P A-fragments (hi/lo) from C-fragment layout ----
        uint32_t ph[4][4], pl[4][4];
#pragma unroll
        for (int kc = 0; kc < 4; kc++) {
            split2(P[2 * kc][0],     P[2 * kc][1],     ph[kc][0], pl[kc][0]);
            split2(P[2 * kc][2],     P[2 * kc][3],     ph[kc][1], pl[kc][1]);
            split2(P[2 * kc + 1][0], P[2 * kc + 1][1], ph[kc][2], pl[kc][2]);
            split2(P[2 * kc + 1][2], P[2 * kc + 1][3], ph[kc][3], pl[kc][3]);
        }

        // ---- PV, 3 error-comp passes (V via ldmatrix.trans) ----
#pragma unroll
        for (int kc = 0; kc < 4; kc++) {
#pragma unroll
            for (int d2 = 0; d2 < 4; d2++) {
                const int row = kc * 16 + (grp & 1) * 8 + i7;
                const uint32_t dbyte = (uint32_t)(d2 * 32 + (grp >> 1) * 16);
                uint32_t bhf[4], blf[4];
                LDSM_X4_T(bhf, VH + SW128((uint32_t)(row * 128) + dbyte));
                LDSM_X4_T(blf, VL + SW128((uint32_t)(row * 128) + dbyte));
                MMA16816(O[d2 * 2],     ph[kc], bhf[0], bhf[1]);
                MMA16816(O[d2 * 2 + 1], ph[kc], bhf[2], bhf[3]);
                MMA16816(O[d2 * 2],     pl[kc], bhf[0], bhf[1]);
                MMA16816(O[d2 * 2 + 1], pl[kc], bhf[2], bhf[3]);
                MMA16816(O[d2 * 2],     ph[kc], blf[0], blf[1]);
                MMA16816(O[d2 * 2 + 1], ph[kc], blf[2], blf[3]);
            }
        }

        // Re-issue into the buffer we just finished reading (2-stage ring).
        if (kb + 2 <= qb) {
            __syncthreads();      // all warps done reading stage kb
            issue_kv(kb + 2);
        }
    }

    // ---- Final l reduction + normalized fp16 write to g_xc ----
    l0 += __shfl_xor_sync(0xFFFFFFFF, l0, 1);
    l0 += __shfl_xor_sync(0xFFFFFFFF, l0, 2);
    l1 += __shfl_xor_sync(0xFFFFFFFF, l1, 1);
    l1 += __shfl_xor_sync(0xFFFFFFFF, l1, 2);
    const float inv0 = 1.0f / l0;
    const float inv1 = 1.0f / l1;

    const int rA = q0 + w * 16 + (lane >> 2);
    const int rB = rA + 8;
    const size_t tA = ((size_t)(b * S_ + rA)) * 1024;
    const size_t tB = ((size_t)(b * S_ + rB)) * 1024;
    const int colbase = h * 64 + (lane & 3) * 2;

#pragma unroll
    for (int dt = 0; dt < 8; dt++) {
        const int col = colbase + dt * 8;
        *(uint32_t*)&g_xc[tA + col] = pack2h(O[dt][0] * inv0, O[dt][1] * inv0);
        *(uint32_t*)&g_xc[tB + col] = pack2h(O[dt][2] * inv1, O[dt][3] * inv1);
    }
}

// ---------------------------------------------------------------------------
extern "C" void kernel_launch(void* const* d_in, const int* in_sizes, int n_in,
                              void* d_out, int out_size)
{
    const float* x  = (const float*)d_in[0];
    const float* Wq = (const float*)d_in[1];
    const float* Wk = (const float*)d_in[2];
    const float* Wv = (const float*)d_in[3];
    const float* Wo = (const float*)d_in[4];
    float* out = (float*)d_out;

    cudaFuncSetAttribute(gemm_qkv, cudaFuncAttributeMaxDynamicSharedMemorySize, GEMM_SMEM);
    cudaFuncSetAttribute(gemm_out, cudaFuncAttributeMaxDynamicSharedMemorySize, GEMM_SMEM);
    cudaFuncSetAttribute(attn_mma, cudaFuncAttributeMaxDynamicSharedMemorySize, ATT_SMEM);

    // One merged prep launch: x fp16 | weight fp16 | rope table
    prep_inputs<<<6208, 256>>>(x, Wq, Wk, Wv, Wo);

    // Merged QKV projections (fp16 single-pass) with fused RoPE + split epilogue
    gemm_qkv<<<dim3(D_ / 128, TOK / 128, 3), 256, GEMM_SMEM>>>();

    attn_mma<<<dim3(S_ / 64, H_, B_), 128, ATT_SMEM>>>();

    gemm_out<<<dim3(D_ / 128, TOK / 128), 256, GEMM_SMEM>>>(out);
}

// round 17
// speedup vs baseline: 2.2711x; 1.0619x over previous
#include <cuda_runtime.h>
#include <cuda_fp16.h>
#include <math.h>
#include <stdint.h>

// Problem constants
#define B_  16
#define S_  512
#define D_  1024
#define H_  16
#define HD_ 64
#define TOK (B_ * S_)            // 8192 tokens

// Scratch (device globals; no dynamic allocation allowed)
__device__ float g_rope[S_][64];              // [s][0:32)=cos, [32:64)=sin

// fp16 activations (single plane): [TOK, 1024]
__device__ __half g_xc[(size_t)TOK * 1024];
// weights: single fp16 plane, 4 x [1024, 1024]
__device__ __half g_wc[4][(size_t)D_ * 1024];
// prepped attention operands (fp16): Q/K hi|lo 2-plane, V single plane
__device__ __half g_qc[(size_t)B_ * H_ * 2 * S_ * 64];
__device__ __half g_kc[(size_t)B_ * H_ * 2 * S_ * 64];
__device__ __half g_vc[(size_t)B_ * H_ * S_ * 64];

#define LOG2E 1.4426950408889634f

// ---------------------------------------------------------------------------
// Helpers (family-portable PTX only: ldmatrix / mma.sync / cp.async)
// ---------------------------------------------------------------------------
__device__ __forceinline__ uint32_t smem_u32(const void* p) {
    uint32_t a;
    asm("{ .reg .u64 t; cvta.to.shared.u64 t, %1; cvt.u32.u64 %0, t; }"
        : "=r"(a) : "l"(p));
    return a;
}

#define SW128(off) ((off) ^ (((off) >> 3) & 0x70))

__device__ __forceinline__ void cp16(uint32_t s, const void* g) {
    asm volatile("cp.async.cg.shared.global [%0], [%1], 16;" :: "r"(s), "l"(g));
}
#define CP_COMMIT() asm volatile("cp.async.commit_group;" ::: "memory")
#define CP_WAIT(n)  asm volatile("cp.async.wait_group %0;" :: "n"(n) : "memory")

#define LDSM_X4(r, addr) \
    asm volatile("ldmatrix.sync.aligned.m8n8.x4.shared.b16 {%0,%1,%2,%3}, [%4];" \
        : "=r"((r)[0]), "=r"((r)[1]), "=r"((r)[2]), "=r"((r)[3]) : "r"(addr))

#define LDSM_X4_T(r, addr) \
    asm volatile("ldmatrix.sync.aligned.m8n8.x4.trans.shared.b16 {%0,%1,%2,%3}, [%4];" \
        : "=r"((r)[0]), "=r"((r)[1]), "=r"((r)[2]), "=r"((r)[3]) : "r"(addr))

// fp16 mma (all matmuls)
#define MMA16816H(d, a, b0, b1) \
    asm volatile("mma.sync.aligned.m16n8k16.row.col.f32.f16.f16.f32 " \
        "{%0,%1,%2,%3}, {%4,%5,%6,%7}, {%8,%9}, {%0,%1,%2,%3};" \
        : "+f"((d)[0]), "+f"((d)[1]), "+f"((d)[2]), "+f"((d)[3]) \
        : "r"((a)[0]), "r"((a)[1]), "r"((a)[2]), "r"((a)[3]), "r"(b0), "r"(b1))

// Split a pair of floats into packed fp16 hi + fp16 lo (exact to ~2^-22)
__device__ __forceinline__ void split2h(float a, float b, uint32_t& hi, uint32_t& lo) {
    __half ah = __float2half_rn(a);
    __half bh = __float2half_rn(b);
    float ar = a - __half2float(ah);
    float br = b - __half2float(bh);
    __half2 hp; hp.x = ah; hp.y = bh;
    __half2 lp; lp.x = __float2half_rn(ar); lp.y = __float2half_rn(br);
    hi = *(uint32_t*)&hp;
    lo = *(uint32_t*)&lp;
}

// Pack a pair of floats into fp16x2 (round-to-nearest)
__device__ __forceinline__ uint32_t pack2h(float a, float b) {
    __half2 hp;
    hp.x = __float2half_rn(a);
    hp.y = __float2half_rn(b);
    return *(uint32_t*)&hp;
}

// ---------------------------------------------------------------------------
// Merged input prep: x fp16 (blocks 0..4095), weights fp16 (blocks
// 4096..6143), rope table (blocks 6144..6207). One launch.
// ---------------------------------------------------------------------------
__global__ void prep_inputs(const float* __restrict__ x,
                            const float* __restrict__ w0, const float* __restrict__ w1,
                            const float* __restrict__ w2, const float* __restrict__ w3)
{
    const int blk = blockIdx.x;
    const int tid = threadIdx.x;

    if (blk < 6144) {
        const float* src;
        __half* dst;
        if (blk < 4096) {
            int i = blk * 256 + tid;
            int row = i >> 7;
            int c8 = (i & 127) * 8;
            src = x + (size_t)row * 1024 + c8;
            dst = g_xc + (size_t)row * 1024 + c8;
        } else {
            int wb = blk - 4096;
            int which = wb >> 9;              // 0..3
            int i = (wb & 511) * 256 + tid;
            int row = i >> 7;
            int c8 = (i & 127) * 8;
            src = ((which == 0) ? w0 : (which == 1) ? w1
                 : (which == 2) ? w2 : w3) + (size_t)row * 1024 + c8;
            dst = g_wc[which] + (size_t)row * 1024 + c8;
        }
        float4 v0 = *(const float4*)(src);
        float4 v1 = *(const float4*)(src + 4);
        uint4 o;
        o.x = pack2h(v0.x, v0.y);
        o.y = pack2h(v0.z, v0.w);
        o.z = pack2h(v1.x, v1.y);
        o.w = pack2h(v1.z, v1.w);
        *(uint4*)dst = o;
    } else {
        // rope table
        int t = (blk - 6144) * 256 + tid;   // 512*32
        int d = t & 31;
        int s = t >> 5;
        float inv = expf(-(float)d * (9.210340371976184f / 32.0f));
        float ang = (float)s * inv;
        float sn, cs;
        sincosf(ang, &sn, &cs);
        g_rope[s][d] = cs;
        g_rope[s][d + 32] = sn;
    }
}

// ---------------------------------------------------------------------------
// fp16 hi/lo plane write for Q/K attention operands (x[0..15]=cols c0..,
// x[16..31]=cols c0+32..), dst layout [plane][S][64].
// ---------------------------------------------------------------------------
__device__ __forceinline__ void prep_write_h(const float* __restrict__ x,
                                             __half* __restrict__ basehi,
                                             int s, int c0)
{
    uint32_t hi[16], lo[16];
#pragma unroll
    for (int p = 0; p < 8; p++)  split2h(x[2 * p], x[2 * p + 1], hi[p], lo[p]);
#pragma unroll
    for (int p = 0; p < 8; p++)  split2h(x[16 + 2 * p], x[17 + 2 * p], hi[8 + p], lo[8 + p]);

    __half* ph = basehi + (size_t)s * 64;
    __half* pl = basehi + (size_t)S_ * 64 + (size_t)s * 64;
    *(uint4*)(ph + c0)      = make_uint4(hi[0], hi[1], hi[2], hi[3]);
    *(uint4*)(ph + c0 + 8)  = make_uint4(hi[4], hi[5], hi[6], hi[7]);
    *(uint4*)(ph + c0 + 32) = make_uint4(hi[8], hi[9], hi[10], hi[11]);
    *(uint4*)(ph + c0 + 40) = make_uint4(hi[12], hi[13], hi[14], hi[15]);
    *(uint4*)(pl + c0)      = make_uint4(lo[0], lo[1], lo[2], lo[3]);
    *(uint4*)(pl + c0 + 8)  = make_uint4(lo[4], lo[5], lo[6], lo[7]);
    *(uint4*)(pl + c0 + 32) = make_uint4(lo[8], lo[9], lo[10], lo[11]);
    *(uint4*)(pl + c0 + 40) = make_uint4(lo[12], lo[13], lo[14], lo[15]);
}

// ---------------------------------------------------------------------------
// HMMA GEMM (fp16 single-pass): C[m,n] = sum_k A[m,k]*W[n,k], K = 1024.
// CTA 128x128 (8 warps, warp tile 64x32), 3-stage cp.async ring, SW128,
// single __syncthreads per chunk, 2 CTAs/SM.
// QKV variant: Q/K -> rope + fp16 hi/lo planes (smem-staged); V -> direct
// fragment write to single fp16 plane. OUT variant: Wo, plain fp32 write.
// ---------------------------------------------------------------------------
#define NCHUNK 16                 // 16 chunks of K=64 fp16
#define TILE_BYTES 16384          // 128 rows x 128 bytes
#define BUF_BYTES  (2 * TILE_BYTES)
#define NSTAGE 3
#define GEMM_SMEM  (NSTAGE * BUF_BYTES)   // 98304

template<bool QKV>
__device__ __forceinline__ void gemm_body(float* __restrict__ out, int zmode)
{
    extern __shared__ char smc[];
    const uint32_t smem_base = smem_u32(smc);
    const int tid  = threadIdx.x;
    const int wid  = tid >> 5;
    const int lane = tid & 31;
    const int wm   = wid >> 2;      // 0..1
    const int wn   = wid & 3;       // 0..3

    const int n0 = blockIdx.x * 128;
    const int m0 = blockIdx.y * 128;

    const __half* __restrict__ Wsrc = g_wc[QKV ? zmode : 3];

    const int r0  = tid >> 3;
    const int c16 = tid & 7;
    const __half* aGm0 = g_xc + (size_t)(m0 + r0) * 1024 + c16 * 8;
    const __half* bGm0 = Wsrc + (size_t)(n0 + r0) * 1024 + c16 * 8;
    const uint32_t aSm0 = SW128((uint32_t)(r0 * 128 + c16 * 16));
    const uint32_t bSm0 = TILE_BYTES + SW128((uint32_t)(r0 * 128 + c16 * 16));

    uint32_t aRow[4];
#pragma unroll
    for (int i = 0; i < 4; i++)
        aRow[i] = (uint32_t)((wm * 64 + i * 16 + (lane & 15)) * 128 + (lane >> 4) * 16);
    uint32_t bRow[2];
#pragma unroll
    for (int g = 0; g < 2; g++)
        bRow[g] = (uint32_t)(TILE_BYTES +
                  (wn * 32 + g * 16 + ((lane >> 4) & 1) * 8 + (lane & 7)) * 128 +
                  ((lane >> 3) & 1) * 16);

    float acc[4][4][4];
#pragma unroll
    for (int i = 0; i < 4; i++)
#pragma unroll
        for (int j = 0; j < 4; j++)
#pragma unroll
            for (int r = 0; r < 4; r++) acc[i][j][r] = 0.f;

    auto issue = [&](int c) {
        const int kc = c * 64;
        const uint32_t base = smem_base + (uint32_t)(c % NSTAGE) * BUF_BYTES;
#pragma unroll
        for (int i = 0; i < 4; i++)
            cp16(base + aSm0 + i * 4096u, aGm0 + kc + (size_t)i * 32 * 1024);
#pragma unroll
        for (int i = 0; i < 4; i++)
            cp16(base + bSm0 + i * 4096u, bGm0 + kc + (size_t)i * 32 * 1024);
        CP_COMMIT();
    };

    issue(0);
    issue(1);

    for (int c = 0; c < NCHUNK; c++) {
        if (c + 2 < NCHUNK) {
            CP_WAIT(1);
            __syncthreads();      // stage c visible; all warps done with stage c-1
            issue(c + 2);         // overwrites stage (c-1)%3 — safe after sync
        } else {
            CP_WAIT(0);
            __syncthreads();
        }

        const uint32_t base = smem_base + (uint32_t)(c % NSTAGE) * BUF_BYTES;
#pragma unroll
        for (int ks = 0; ks < 4; ks++) {
            const uint32_t kb32 = (uint32_t)(ks * 32);
            uint32_t af[4][4], bf[2][4];
#pragma unroll
            for (int i = 0; i < 4; i++)
                LDSM_X4(af[i], base + SW128(aRow[i] + kb32));
#pragma unroll
            for (int g = 0; g < 2; g++)
                LDSM_X4(bf[g], base + SW128(bRow[g] + kb32));
#pragma unroll
            for (int i = 0; i < 4; i++) {
#pragma unroll
                for (int j = 0; j < 4; j++) {
                    const uint32_t* bb = bf[j >> 1];
                    MMA16816H(acc[i][j], af[i], bb[(j & 1) * 2], bb[(j & 1) * 2 + 1]);
                }
            }
        }
    }

    const int r4 = lane >> 2;
    const int c2 = (lane & 3) * 2;

    if (!QKV) {
        // Plain fp32 epilogue
#pragma unroll
        for (int i = 0; i < 4; i++) {
            const int mbase = m0 + wm * 64 + i * 16 + r4;
#pragma unroll
            for (int j = 0; j < 4; j++) {
                const int n = n0 + wn * 32 + j * 8 + c2;
#pragma unroll
                for (int rr = 0; rr < 2; rr++) {
                    const int m = mbase + rr * 8;
                    float2 val;
                    val.x = acc[i][j][rr * 2 + 0];
                    val.y = acc[i][j][rr * 2 + 1];
                    *(float2*)(out + (size_t)m * D_ + n) = val;
                }
            }
        }
        return;
    }

    if (zmode == 2) {
        // ---- V epilogue: direct fragment write (no rope, single fp16 plane)
#pragma unroll
        for (int i = 0; i < 4; i++) {
            const int mbase = m0 + wm * 64 + i * 16 + r4;
#pragma unroll
            for (int j = 0; j < 4; j++) {
                const int n = n0 + wn * 32 + j * 8 + c2;
                const int h = n >> 6, d = n & 63;
#pragma unroll
                for (int rr = 0; rr < 2; rr++) {
                    const int m = mbase + rr * 8;
                    const int b = m >> 9, s = m & 511;
                    *(uint32_t*)&g_vc[((size_t)(b * H_ + h) * S_ + s) * 64 + d] =
                        pack2h(acc[i][j][rr * 2 + 0], acc[i][j][rr * 2 + 1]);
                }
            }
        }
        return;
    }

    // ---- Q/K epilogue: stage fp32 tile via ring smem, rope + fp16 split ----
    __syncthreads();              // all warps done with last LDSM reads
    float* sf = (float*)smc;      // reuse ring: 128 x 132 fp32 (67.5 KB)
#pragma unroll
    for (int i = 0; i < 4; i++) {
#pragma unroll
        for (int j = 0; j < 4; j++) {
            const int nl = wn * 32 + j * 8 + c2;
#pragma unroll
            for (int rr = 0; rr < 2; rr++) {
                const int ml = wm * 64 + i * 16 + rr * 8 + r4;
                sf[ml * 132 + nl]     = acc[i][j][rr * 2 + 0];
                sf[ml * 132 + nl + 1] = acc[i][j][rr * 2 + 1];
            }
        }
    }
    __syncthreads();

    __half* dstbase = (zmode == 0) ? g_qc : g_kc;

#pragma unroll
    for (int it = 0; it < 2; it++) {
        const int u    = tid + 256 * it;       // 512 units: 128 rows x 2 heads x 2 halves
        const int r    = u >> 2;
        const int hh   = (u >> 1) & 1;
        const int half = u & 1;
        const int c0   = half * 16;

        const int m = m0 + r;
        const int s = m & 511;
        const int bcur = m >> 9;
        const int hglob = (n0 >> 6) + hh;
        const size_t plane = (size_t)(bcur * H_ + hglob) * 2 * S_ * 64;

        const float* srow = sf + r * 132 + hh * 64;
        float x[32];
#pragma unroll
        for (int j2 = 0; j2 < 4; j2++) {
            *(float4*)&x[j2 * 4]      = *(const float4*)(srow + c0 + j2 * 4);
            *(float4*)&x[16 + j2 * 4] = *(const float4*)(srow + c0 + 32 + j2 * 4);
        }

        {
            const float* tab = g_rope[s];
            const float sc = (zmode == 0) ? 0.125f : 1.0f;
#pragma unroll
            for (int j2 = 0; j2 < 16; j2++) {
                const float csv = tab[c0 + j2] * sc;
                const float snv = tab[c0 + j2 + 32] * sc;
                const float a = x[j2], b2v = x[16 + j2];
                x[j2]      = a * csv - b2v * snv;
                x[16 + j2] = b2v * csv + a * snv;
            }
        }
        prep_write_h(x, dstbase + plane, s, c0);
    }
}

__global__ void __launch_bounds__(256, 2) gemm_qkv()
{
    gemm_body<true>(nullptr, blockIdx.z);
}

__global__ void __launch_bounds__(256, 2) gemm_out(float* __restrict__ out)
{
    gemm_body<false>(out, 3);
}

// ---------------------------------------------------------------------------
// HMMA causal flash attention (fp16). QK: 3 exact-split passes; PV: exact
// P hi/lo x single-fp16 V (2 passes). Block = (qb, h, b); 128 threads.
// Q fragments direct from gmem; 2-stage KV ring (2 x 24KB) -> 3 CTAs/SM.
// Epilogue writes fp16 (single plane) to g_xc for the OUT GEMM.
// ---------------------------------------------------------------------------
#define ATT_STB  24576
#define ATT_SMEM (2 * ATT_STB)   // 49152

// cp.async one 64x64 fp16 plane (8KB) into SW128-swizzled smem
__device__ __forceinline__ void cpa_plane(uint32_t dst, const __half* __restrict__ src,
                                          int tid)
{
#pragma unroll
    for (int i = 0; i < 4; i++) {
        int u = tid + 128 * i;
        int r = u >> 3, ch = u & 7;
        cp16(dst + SW128((uint32_t)(r * 128 + ch * 16)), src + (size_t)r * 64 + ch * 8);
    }
}

__global__ void __launch_bounds__(128, 3) attn_mma()
{
    extern __shared__ char sm[];
    const uint32_t sb = smem_u32(sm);

    const int tid  = threadIdx.x;
    const int lane = tid & 31;
    const int w    = tid >> 5;
    const int qb = blockIdx.x;
    const int h  = blockIdx.y;
    const int b  = blockIdx.z;
    const int q0 = qb * 64;
    const int bh = b * H_ + h;

    const size_t LO = (size_t)S_ * 64;
    const __half* Qc = g_qc + (size_t)bh * 2 * S_ * 64;
    const __half* Kc = g_kc + (size_t)bh * 2 * S_ * 64;
    const __half* Vc = g_vc + (size_t)bh * S_ * 64;

    const int i7  = lane & 7;
    const int grp = lane >> 3;

    auto issue_kv = [&](int kb) {
        const uint32_t st = sb + (uint32_t)(kb & 1) * ATT_STB;
        const int k0 = kb * 64;
        cpa_plane(st,         Kc + (size_t)k0 * 64,      tid);
        cpa_plane(st + 8192,  Kc + LO + (size_t)k0 * 64, tid);
        cpa_plane(st + 16384, Vc + (size_t)k0 * 64,      tid);
        CP_COMMIT();
    };

    issue_kv(0);
    if (qb >= 1) issue_kv(1);

    // ---- Q fragments straight from gmem (mma A-layout) ----
    uint32_t qh[4][4], ql[4][4];
    {
        const int rowA = q0 + w * 16 + (lane >> 2);
        const int rowB = rowA + 8;
        const int cc = (lane & 3) * 2;
#pragma unroll
        for (int kc = 0; kc < 4; kc++) {
            const int col = kc * 16 + cc;
            qh[kc][0] = *(const uint32_t*)&Qc[(size_t)rowA * 64 + col];
            qh[kc][1] = *(const uint32_t*)&Qc[(size_t)rowB * 64 + col];
            qh[kc][2] = *(const uint32_t*)&Qc[(size_t)rowA * 64 + col + 8];
            qh[kc][3] = *(const uint32_t*)&Qc[(size_t)rowB * 64 + col + 8];
            ql[kc][0] = *(const uint32_t*)&Qc[LO + (size_t)rowA * 64 + col];
            ql[kc][1] = *(const uint32_t*)&Qc[LO + (size_t)rowB * 64 + col];
            ql[kc][2] = *(const uint32_t*)&Qc[LO + (size_t)rowA * 64 + col + 8];
            ql[kc][3] = *(const uint32_t*)&Qc[LO + (size_t)rowB * 64 + col + 8];
        }
    }

    float mr0 = -1e30f, mr1 = -1e30f;
    float l0 = 0.f, l1 = 0.f;
    float O[8][4];
#pragma unroll
    for (int i = 0; i < 8; i++)
#pragma unroll
        for (int j = 0; j < 4; j++) O[i][j] = 0.f;

    for (int kb = 0; kb <= qb; kb++) {
        if (kb + 1 <= qb) { CP_WAIT(1); } else { CP_WAIT(0); }
        __syncthreads();          // stage kb ready for all warps

        const uint32_t st = sb + (uint32_t)(kb & 1) * ATT_STB;
        const uint32_t KH = st, KL = st + 8192, VP = st + 16384;

        // ---- Scores S[64q x 64k] per warp, 3 exact-split passes ----
        float S[8][4];
#pragma unroll
        for (int i = 0; i < 8; i++)
#pragma unroll
            for (int j = 0; j < 4; j++) S[i][j] = 0.f;

#pragma unroll
        for (int kc = 0; kc < 4; kc++) {
#pragma unroll
            for (int n2 = 0; n2 < 4; n2++) {
                const int row = n2 * 16 + (grp >> 1) * 8 + i7;
                const uint32_t kbyte = (uint32_t)(kc * 32 + (grp & 1) * 16);
                uint32_t bhf[4], blf[4];
                LDSM_X4(bhf, KH + SW128((uint32_t)(row * 128) + kbyte));
                LDSM_X4(blf, KL + SW128((uint32_t)(row * 128) + kbyte));
                MMA16816H(S[n2 * 2],     qh[kc], bhf[0], bhf[1]);
                MMA16816H(S[n2 * 2 + 1], qh[kc], bhf[2], bhf[3]);
                MMA16816H(S[n2 * 2],     ql[kc], bhf[0], bhf[1]);
                MMA16816H(S[n2 * 2 + 1], ql[kc], bhf[2], bhf[3]);
                MMA16816H(S[n2 * 2],     qh[kc], blf[0], blf[1]);
                MMA16816H(S[n2 * 2 + 1], qh[kc], blf[2], blf[3]);
            }
        }

        // ---- Causal mask (diagonal block only) ----
        if (kb == qb) {
            const int rloc0 = w * 16 + (lane >> 2);
            const int cbase = (lane & 3) * 2;
#pragma unroll
            for (int jt = 0; jt < 8; jt++) {
                const int c = jt * 8 + cbase;
                if (c     > rloc0)     S[jt][0] = -1e30f;
                if (c + 1 > rloc0)     S[jt][1] = -1e30f;
                if (c     > rloc0 + 8) S[jt][2] = -1e30f;
                if (c + 1 > rloc0 + 8) S[jt][3] = -1e30f;
            }
        }

        // ---- Online softmax ----
        float bm0 = -1e30f, bm1 = -1e30f;
#pragma unroll
        for (int jt = 0; jt < 8; jt++) {
            bm0 = fmaxf(bm0, fmaxf(S[jt][0], S[jt][1]));
            bm1 = fmaxf(bm1, fmaxf(S[jt][2], S[jt][3]));
        }
        bm0 = fmaxf(bm0, __shfl_xor_sync(0xFFFFFFFF, bm0, 1));
        bm0 = fmaxf(bm0, __shfl_xor_sync(0xFFFFFFFF, bm0, 2));
        bm1 = fmaxf(bm1, __shfl_xor_sync(0xFFFFFFFF, bm1, 1));
        bm1 = fmaxf(bm1, __shfl_xor_sync(0xFFFFFFFF, bm1, 2));

        const float mn0 = fmaxf(mr0, bm0);
        const float mn1 = fmaxf(mr1, bm1);
        const float corr0 = exp2f((mr0 - mn0) * LOG2E);
        const float corr1 = exp2f((mr1 - mn1) * LOG2E);
        mr0 = mn0; mr1 = mn1;
        l0 *= corr0; l1 *= corr1;

        float P[8][4];
#pragma unroll
        for (int jt = 0; jt < 8; jt++) {
            P[jt][0] = exp2f((S[jt][0] - mn0) * LOG2E);
            P[jt][1] = exp2f((S[jt][1] - mn0) * LOG2E);
            P[jt][2] = exp2f((S[jt][2] - mn1) * LOG2E);
            P[jt][3] = exp2f((S[jt][3] - mn1) * LOG2E);
            l0 += P[jt][0] + P[jt][1];
            l1 += P[jt][2] + P[jt][3];
        }
#pragma unroll
        for (int dt = 0; dt < 8; dt++) {
            O[dt][0] *= corr0; O[dt][1] *= corr0;
            O[dt][2] *= corr1; O[dt][3] *= corr1;
        }

        // ---- P A-fragments (fp16 hi/lo, exact split) ----
        uint32_t ph[4][4], pl[4][4];
#pragma unroll
        for (int kc = 0; kc < 4; kc++) {
            split2h(P[2 * kc][0],     P[2 * kc][1],     ph[kc][0], pl[kc][0]);
            split2h(P[2 * kc][2],     P[2 * kc][3],     ph[kc][1], pl[kc][1]);
            split2h(P[2 * kc + 1][0], P[2 * kc + 1][1], ph[kc][2], pl[kc][2]);
            split2h(P[2 * kc + 1][2], P[2 * kc + 1][3], ph[kc][3], pl[kc][3]);
        }

        // ---- PV, 2 passes (P exact split x single-fp16 V via ldmatrix.trans)
#pragma unroll
        for (int kc = 0; kc < 4; kc++) {
#pragma unroll
            for (int d2 = 0; d2 < 4; d2++) {
                const int row = kc * 16 + (grp & 1) * 8 + i7;
                const uint32_t dbyte = (uint32_t)(d2 * 32 + (grp >> 1) * 16);
                uint32_t bvf[4];
                LDSM_X4_T(bvf, VP + SW128((uint32_t)(row * 128) + dbyte));
                MMA16816H(O[d2 * 2],     ph[kc], bvf[0], bvf[1]);
                MMA16816H(O[d2 * 2 + 1], ph[kc], bvf[2], bvf[3]);
                MMA16816H(O[d2 * 2],     pl[kc], bvf[0], bvf[1]);
                MMA16816H(O[d2 * 2 + 1], pl[kc], bvf[2], bvf[3]);
            }
        }

        // Re-issue into the buffer we just finished reading (2-stage ring).
        if (kb + 2 <= qb) {
            __syncthreads();      // all warps done reading stage kb
            issue_kv(kb + 2);
        }
    }

    // ---- Final l reduction + normalized fp16 write to g_xc ----
    l0 += __shfl_xor_sync(0xFFFFFFFF, l0, 1);
    l0 += __shfl_xor_sync(0xFFFFFFFF, l0, 2);
    l1 += __shfl_xor_sync(0xFFFFFFFF, l1, 1);
    l1 += __shfl_xor_sync(0xFFFFFFFF, l1, 2);
    const float inv0 = 1.0f / l0;
    const float inv1 = 1.0f / l1;

    const int rA = q0 + w * 16 + (lane >> 2);
    const int rB = rA + 8;
    const size_t tA = ((size_t)(b * S_ + rA)) * 1024;
    const size_t tB = ((size_t)(b * S_ + rB)) * 1024;
    const int colbase = h * 64 + (lane & 3) * 2;

#pragma unroll
    for (int dt = 0; dt < 8; dt++) {
        const int col = colbase + dt * 8;
        *(uint32_t*)&g_xc[tA + col] = pack2h(O[dt][0] * inv0, O[dt][1] * inv0);
        *(uint32_t*)&g_xc[tB + col] = pack2h(O[dt][2] * inv1, O[dt][3] * inv1);
    }
}

// ---------------------------------------------------------------------------
extern "C" void kernel_launch(void* const* d_in, const int* in_sizes, int n_in,
                              void* d_out, int out_size)
{
    const float* x  = (const float*)d_in[0];
    const float* Wq = (const float*)d_in[1];
    const float* Wk = (const float*)d_in[2];
    const float* Wv = (const float*)d_in[3];
    const float* Wo = (const float*)d_in[4];
    float* out = (float*)d_out;

    cudaFuncSetAttribute(gemm_qkv, cudaFuncAttributeMaxDynamicSharedMemorySize, GEMM_SMEM);
    cudaFuncSetAttribute(gemm_out, cudaFuncAttributeMaxDynamicSharedMemorySize, GEMM_SMEM);
    cudaFuncSetAttribute(attn_mma, cudaFuncAttributeMaxDynamicSharedMemorySize, ATT_SMEM);

    // One merged prep launch: x fp16 | weight fp16 | rope table
    prep_inputs<<<6208, 256>>>(x, Wq, Wk, Wv, Wo);

    // Merged QKV projections (fp16 single-pass) with fused epilogues
    gemm_qkv<<<dim3(D_ / 128, TOK / 128, 3), 256, GEMM_SMEM>>>();

    attn_mma<<<dim3(S_ / 64, H_, B_), 128, ATT_SMEM>>>();

    gemm_out<<<dim3(D_ / 128, TOK / 128), 256, GEMM_SMEM>>>(out);
}